// round 8
// baseline (speedup 1.0000x reference)
#include <cuda_runtime.h>
#include <cuda_fp16.h>
#include <math.h>
#include <cstdint>

// Problem constants
#define BATCH 4
#define SEQ   4096
#define DIM   512
#define KEXP  8
#define ROWS  (BATCH*SEQ)        // 16384 token rows
#define CHUNK 128                // scan chunk length
#define NCHUNK (SEQ/CHUNK)       // 32 chunks
#define INV_TAU (1.0f/16.0f)
#define LN_EPS 1e-5f

// ---------------------------------------------------------------------------
// Scratch (static device globals)
// ---------------------------------------------------------------------------
__device__ float g_i[ROWS * DIM];                       // x @ W_i (fp32)
__device__ float g_e[ROWS * KEXP];
__device__ float g_s[ROWS * KEXP];
__device__ float g_S[BATCH * NCHUNK * KEXP * DIM];
__device__ float g_P[BATCH * NCHUNK * KEXP * DIM];
__device__ __half g_xhi[ROWS * DIM];
__device__ __half g_xlo[ROWS * DIM];
__device__ __half g_yhi[ROWS * DIM];
__device__ __half g_ylo[ROWS * DIM];
__device__ __half g_wi[DIM * DIM];                      // W_i^T  [N,K] fp16
__device__ __half g_wo[DIM * DIM];                      // W_out^T [N,K] fp16
__device__ __half g_wes[16 * DIM];                      // [W_e|W_s]^T [16,K] fp16

__device__ __forceinline__ void split_half(float v, __half& h, __half& l) {
    h = __float2half(v);
    l = __float2half(v - __half2float(h));
}

// ---------------------------------------------------------------------------
// PTX primitives (baseline sm_80+ — legal for compute_103 PTX target)
// ---------------------------------------------------------------------------
__device__ __forceinline__ uint32_t smem_to_u32(const void* p) {
    uint32_t a;
    asm("{ .reg .u64 t; cvta.to.shared.u64 t, %1; cvt.u32.u64 %0, t; }" : "=r"(a) : "l"(p));
    return a;
}

__device__ __forceinline__ void cp16(uint32_t dst, const void* src) {
    asm volatile("cp.async.cg.shared.global [%0], [%1], 16;" :: "r"(dst), "l"(src));
}
__device__ __forceinline__ void cp_commit() {
    asm volatile("cp.async.commit_group;" ::: "memory");
}
template <int N>
__device__ __forceinline__ void cp_wait() {
    asm volatile("cp.async.wait_group %0;" :: "n"(N) : "memory");
}

__device__ __forceinline__ void ldsm4(uint32_t* r, uint32_t addr) {
    asm volatile("ldmatrix.sync.aligned.m8n8.x4.shared.b16 {%0,%1,%2,%3}, [%4];"
                 : "=r"(r[0]), "=r"(r[1]), "=r"(r[2]), "=r"(r[3]) : "r"(addr));
}

__device__ __forceinline__ void mma16816(float* c, const uint32_t* a, const uint32_t* b) {
    asm volatile(
        "mma.sync.aligned.m16n8k16.row.col.f32.f16.f16.f32 "
        "{%0,%1,%2,%3}, {%4,%5,%6,%7}, {%8,%9}, {%0,%1,%2,%3};"
        : "+f"(c[0]), "+f"(c[1]), "+f"(c[2]), "+f"(c[3])
        : "r"(a[0]), "r"(a[1]), "r"(a[2]), "r"(a[3]), "r"(b[0]), "r"(b[1]));
}

// Swizzle: XOR bits[4:5] with bits[7:8]. MUST be applied to the final 16B-chunk
// offset (never add offsets after swizzling — carry corrupts the row index).
__device__ __forceinline__ uint32_t swz(uint32_t off) {
    return off ^ (((off >> 7) & 3u) << 4);
}

// ---------------------------------------------------------------------------
// HMMA 2-term fp16 GEMM: C[Mx512] = (Ahi+Alo) * B^T
// CTA tile 128(M)x128(N), 8 warps of 64x32 (2M x 4N), BK=32.
// 4-stage cp.async ring in 96KB dynamic SMEM, ONE __syncthreads per k-iter.
// ---------------------------------------------------------------------------
#define BK 32
#define NKI2 (DIM/BK)            // 16 k-iterations
#define GTILE_B 8192             // bytes per tile (128 rows x 64B)
#define GSTAGES 4
#define GSM_TOTAL (GSTAGES*3*GTILE_B)   // 98304 bytes

__device__ __forceinline__ void gemm_load(uint32_t sbase, int stage, int c,
                                          const __half* Ahi, const __half* Alo,
                                          const __half* B,
                                          int row0, int col0, int tid) {
    const int r = tid >> 1;              // 0..127
    const int h = tid & 1;               // 32B half of the 64B row
    const uint32_t so0 = swz((uint32_t)(r * 64 + h * 32));
    const uint32_t so1 = swz((uint32_t)(r * 64 + h * 32 + 16));
    const size_t ga = (size_t)(row0 + r) * DIM + c * BK + h * 16;
    const size_t gb = (size_t)(col0 + r) * DIM + c * BK + h * 16;
    const uint32_t base = sbase + (uint32_t)(stage * 3 * GTILE_B);
    cp16(base + 0 * GTILE_B + so0, Ahi + ga);
    cp16(base + 0 * GTILE_B + so1, Ahi + ga + 8);
    cp16(base + 1 * GTILE_B + so0, Alo + ga);
    cp16(base + 1 * GTILE_B + so1, Alo + ga + 8);
    cp16(base + 2 * GTILE_B + so0, B + gb);
    cp16(base + 2 * GTILE_B + so1, B + gb + 8);
}

__device__ __forceinline__ void gemm_body(char* dsm,
                                          const __half* __restrict__ Ahi,
                                          const __half* __restrict__ Alo,
                                          const __half* __restrict__ B,
                                          float* __restrict__ C) {
    const uint32_t sbase = smem_to_u32(dsm);
    const int tid = threadIdx.x;
    const int lane = tid & 31;
    const int wid = tid >> 5;
    const int warp_m = wid >> 2;         // 0..1 -> 64-row slice
    const int warp_n = wid & 3;          // 0..3 -> 32-col slice
    const int row0 = blockIdx.y * 128;
    const int col0 = blockIdx.x * 128;

    const int lr = lane & 15;
    const int lc = (lane >> 4) & 1;

    float acc[4][4][4];
    #pragma unroll
    for (int m = 0; m < 4; m++)
        #pragma unroll
        for (int n = 0; n < 4; n++)
            #pragma unroll
            for (int q = 0; q < 4; q++) acc[m][n][q] = 0.0f;

    // Prologue: fill stages 0..2
    #pragma unroll
    for (int s = 0; s < GSTAGES - 1; ++s) {
        gemm_load(sbase, s, s, Ahi, Alo, B, row0, col0, tid);
        cp_commit();
    }

    // ldmatrix offsets: swizzle applied LAST, per (tile-row, k-half)
    uint32_t aOff[4][2], bOff[2][2];
    #pragma unroll
    for (int m = 0; m < 4; m++)
        #pragma unroll
        for (int kk = 0; kk < 2; kk++)
            aOff[m][kk] = swz((uint32_t)((warp_m * 64 + m * 16 + lr) * 64
                                         + lc * 16 + kk * 32));
    #pragma unroll
    for (int q = 0; q < 2; q++)
        #pragma unroll
        for (int kk = 0; kk < 2; kk++)
            bOff[q][kk] = swz((uint32_t)((warp_n * 32 + q * 16 + lr) * 64
                                         + lc * 16 + kk * 32));

    for (int c = 0; c < NKI2; ++c) {
        cp_wait<GSTAGES - 2>();          // stage c resident
        __syncthreads();                 // all warps done with stage c-1

        if (c + GSTAGES - 1 < NKI2)
            gemm_load(sbase, (c + GSTAGES - 1) & (GSTAGES - 1), c + GSTAGES - 1,
                      Ahi, Alo, B, row0, col0, tid);
        cp_commit();                     // uniform one group per iter

        const uint32_t bb = sbase + (uint32_t)((c & (GSTAGES - 1)) * 3 * GTILE_B);

        #pragma unroll
        for (int kk = 0; kk < 2; ++kk) {
            uint32_t a[4][4], b[4][2];

            // B fragments: 2 LDSM.x4 -> 4 n8-tiles (shared by both combos)
            #pragma unroll
            for (int q = 0; q < 2; q++) {
                uint32_t t4[4];
                ldsm4(t4, bb + 2 * GTILE_B + bOff[q][kk]);
                b[2*q][0] = t4[0]; b[2*q+1][0] = t4[1];
                b[2*q][1] = t4[2]; b[2*q+1][1] = t4[3];
            }

            // combo 1: Ahi x B
            #pragma unroll
            for (int m = 0; m < 4; m++)
                ldsm4(a[m], bb + 0 * GTILE_B + aOff[m][kk]);
            #pragma unroll
            for (int m = 0; m < 4; m++)
                #pragma unroll
                for (int n = 0; n < 4; n++) mma16816(acc[m][n], a[m], b[n]);

            // combo 2: Alo x B
            #pragma unroll
            for (int m = 0; m < 4; m++)
                ldsm4(a[m], bb + 1 * GTILE_B + aOff[m][kk]);
            #pragma unroll
            for (int m = 0; m < 4; m++)
                #pragma unroll
                for (int n = 0; n < 4; n++) mma16816(acc[m][n], a[m], b[n]);
        }
    }

    // Epilogue
    const int tr = lane >> 2;
    const int tc = (lane & 3) * 2;
    #pragma unroll
    for (int m = 0; m < 4; m++) {
        const int rbase = row0 + warp_m * 64 + m * 16 + tr;
        #pragma unroll
        for (int n = 0; n < 4; n++) {
            const int col = col0 + warp_n * 32 + n * 8 + tc;
            float* p0 = C + (size_t)rbase * DIM + col;
            float* p1 = C + (size_t)(rbase + 8) * DIM + col;
            *(float2*)p0 = make_float2(acc[m][n][0], acc[m][n][1]);
            *(float2*)p1 = make_float2(acc[m][n][2], acc[m][n][3]);
        }
    }
}

__global__ __launch_bounds__(256, 2) void gemm1_kernel() {
    extern __shared__ char dsm[];
    gemm_body(dsm, g_xhi, g_xlo, g_wi, g_i);
}
__global__ __launch_bounds__(256, 2) void gemm2_kernel(float* __restrict__ out) {
    extern __shared__ char dsm[];
    gemm_body(dsm, g_yhi, g_ylo, g_wo, out);
}

// ---------------------------------------------------------------------------
// es via HMMA: [e|s][Mx16] = (xhi+xlo) * Wes^T. 32B-row tiles, 3-stage ring.
// (32B pitch: no offsets are added post-swizzle anywhere.)
// ---------------------------------------------------------------------------
#define ETILE_B 4096             // 128 rows x 32B
#define ES_PITCH 520
#define ESTAGES 3
#define ENKI 32                  // k16 iterations

struct __align__(128) EsSmem {
    char abuf[ESTAGES][2][ETILE_B];  // 24 KB
    __half w[16 * ES_PITCH];         // 16640 B
};

__device__ __forceinline__ void es_load(uint32_t sbase, int stage, int c,
                                        int row0, int r) {
    #pragma unroll
    for (int j = 0; j < 4; ++j) {
        const int tile = j >> 1, h = j & 1;
        const __half* src = tile ? g_xlo : g_xhi;
        cp16(sbase + (uint32_t)((stage * 2 + tile) * ETILE_B)
                   + swz((uint32_t)(r * 32 + h * 16)),
             src + (size_t)(row0 + r) * DIM + c * 16 + h * 8);
    }
}

__global__ __launch_bounds__(128, 3) void es_mma_kernel() {
    __shared__ EsSmem sm;
    const uint32_t sbase = smem_to_u32(&sm);
    const uint32_t wbase = smem_to_u32(sm.w);
    const int tid = threadIdx.x;
    const int lane = tid & 31;
    const int wid = tid >> 5;            // 0..3
    const int row0 = blockIdx.x * 128;
    const int r = tid;

    // Fill W smem: 16 rows x 512 halves, pitch ES_PITCH halves
    {
        const int row = tid >> 3;              // 0..15
        const int colb = (tid & 7) * 64;       // 0..448
        #pragma unroll
        for (int q = 0; q < 8; ++q) {
            uint4 v = *(const uint4*)(g_wes + row * DIM + colb + q * 8);
            *(uint4*)(sm.w + row * ES_PITCH + colb + q * 8) = v;
        }
    }

    #pragma unroll
    for (int s = 0; s < ESTAGES - 1; ++s) {
        es_load(sbase, s, s, row0, r);
        cp_commit();
    }

    const int lr = lane & 15;
    const int lc = (lane >> 4) & 1;
    uint32_t aAddr[2];
    #pragma unroll
    for (int m = 0; m < 2; m++)
        aAddr[m] = swz((uint32_t)((wid * 32 + m * 16 + lr) * 32 + lc * 16));

    float acc[2][2][4];
    #pragma unroll
    for (int m = 0; m < 2; m++)
        #pragma unroll
        for (int n = 0; n < 2; n++)
            #pragma unroll
            for (int q = 0; q < 4; q++) acc[m][n][q] = 0.0f;

    for (int c = 0; c < ENKI; ++c) {
        cp_wait<ESTAGES - 2>();
        __syncthreads();

        if (c + ESTAGES - 1 < ENKI) {
            int st = (c + ESTAGES - 1) % ESTAGES;
            es_load(sbase, st, c + ESTAGES - 1, row0, r);
        }
        cp_commit();

        uint32_t b[2][2];
        #pragma unroll
        for (int nt = 0; nt < 2; ++nt) {
            const uint32_t base = wbase
                + (uint32_t)(((nt * 8 + (lane >> 2)) * ES_PITCH + c * 16 + (lane & 3) * 2) * 2);
            asm volatile("ld.shared.b32 %0, [%1];" : "=r"(b[nt][0]) : "r"(base));
            asm volatile("ld.shared.b32 %0, [%1];" : "=r"(b[nt][1]) : "r"(base + 16));
        }

        const uint32_t ab = sbase + (uint32_t)((c % ESTAGES) * 2 * ETILE_B);
        uint32_t a[4];
        #pragma unroll
        for (int m = 0; m < 2; m++) {
            ldsm4(a, ab + aAddr[m]);
            mma16816(acc[m][0], a, b[0]);
            mma16816(acc[m][1], a, b[1]);
        }
        #pragma unroll
        for (int m = 0; m < 2; m++) {
            ldsm4(a, ab + ETILE_B + aAddr[m]);
            mma16816(acc[m][0], a, b[0]);
            mma16816(acc[m][1], a, b[1]);
        }
    }

    const int tr = lane >> 2;
    const int tc = (lane & 3) * 2;
    #pragma unroll
    for (int m = 0; m < 2; m++) {
        const int rbase = row0 + wid * 32 + m * 16 + tr;
        #pragma unroll
        for (int nt = 0; nt < 2; nt++) {
            float* dst = nt ? g_s : g_e;
            *(float2*)(dst + (size_t)rbase * KEXP + tc) =
                make_float2(acc[m][nt][0], acc[m][nt][1]);
            *(float2*)(dst + (size_t)(rbase + 8) * KEXP + tc) =
                make_float2(acc[m][nt][2], acc[m][nt][3]);
        }
    }
}

// ---------------------------------------------------------------------------
// Conversions
// ---------------------------------------------------------------------------
__global__ __launch_bounds__(256) void convert_x_kernel(const float* __restrict__ x) {
    const size_t i = (size_t)blockIdx.x * 256 + threadIdx.x;   // float4 index
    float4 v = ((const float4*)x)[i];
    __half h[4], l[4];
    split_half(v.x, h[0], l[0]);
    split_half(v.y, h[1], l[1]);
    split_half(v.z, h[2], l[2]);
    split_half(v.w, h[3], l[3]);
    ((uint2*)g_xhi)[i] = *(uint2*)h;
    ((uint2*)g_xlo)[i] = *(uint2*)l;
}

__global__ __launch_bounds__(256) void convert_w_kernel(const float* __restrict__ W_i,
                                                        const float* __restrict__ W_out) {
    __shared__ float t[32][33];
    const int z = blockIdx.z;
    const float* W = z ? W_out : W_i;
    __half* D = z ? g_wo : g_wi;
    const int n0 = blockIdx.x * 32, k0 = blockIdx.y * 32;
    const int tx = threadIdx.x, ty = threadIdx.y;
    #pragma unroll
    for (int j = 0; j < 4; ++j)
        t[ty + j * 8][tx] = W[(size_t)(k0 + ty + j * 8) * DIM + n0 + tx];
    __syncthreads();
    #pragma unroll
    for (int j = 0; j < 4; ++j) {
        const int nn = ty + j * 8;
        D[(size_t)(n0 + nn) * DIM + k0 + tx] = __float2half(t[tx][nn]);
    }
}

__global__ __launch_bounds__(256) void convert_wes_kernel(const float* __restrict__ W_e,
                                                          const float* __restrict__ W_s) {
    for (int e = threadIdx.x; e < 16 * DIM; e += 256) {
        const int j = e >> 9, d = e & 511;
        const float v = (j < 8) ? W_e[d * KEXP + j] : W_s[d * KEXP + j - 8];
        g_wes[e] = __float2half(v);
    }
}

// ---------------------------------------------------------------------------
// Decay helper
// ---------------------------------------------------------------------------
__device__ __forceinline__ void load_decay(const float* __restrict__ o_param,
                                           int d, float scale, float o[KEXP]) {
    #pragma unroll
    for (int k = 0; k < KEXP; k++) {
        float op = o_param[k * DIM + d];
        float ls = fminf(op, 0.0f) - log1pf(expf(-fabsf(op)));
        o[k] = expf(ls * scale);
    }
}

// ---------------------------------------------------------------------------
// Scan phase 1: per-chunk local end state
// ---------------------------------------------------------------------------
__global__ __launch_bounds__(DIM) void scan_local_kernel(const float* __restrict__ o_param) {
    const int c = blockIdx.x, b = blockIdx.y, d = threadIdx.x;
    float o[KEXP], m[KEXP];
    load_decay(o_param, d, INV_TAU, o);
    #pragma unroll
    for (int k = 0; k < KEXP; k++) m[k] = 0.0f;

    const int t0 = c * CHUNK;
    const float* ip = g_i + ((size_t)b * SEQ + t0) * DIM + d;
    const float* ep = g_e + ((size_t)b * SEQ + t0) * KEXP;

    #pragma unroll 2
    for (int t = 0; t < CHUNK; t++) {
        float iv = ip[(size_t)t * DIM];
        float4 e0 = *(const float4*)(ep + t * KEXP);
        float4 e1 = *(const float4*)(ep + t * KEXP + 4);
        float ev[KEXP] = {e0.x, e0.y, e0.z, e0.w, e1.x, e1.y, e1.z, e1.w};
        #pragma unroll
        for (int k = 0; k < KEXP; k++)
            m[k] = fmaf(o[k], m[k], ev[k] * iv);
    }
    #pragma unroll
    for (int k = 0; k < KEXP; k++)
        g_S[(((size_t)b * NCHUNK + c) * KEXP + k) * DIM + d] = m[k];
}

// ---------------------------------------------------------------------------
// Scan phase 2: prefix over chunks; loads hoisted for MLP.
// ---------------------------------------------------------------------------
__global__ __launch_bounds__(DIM) void scan_prefix_kernel(const float* __restrict__ o_param) {
    const int b = blockIdx.x;
    const int kp = blockIdx.y * 2;
    const int d = threadIdx.x;

    float oL0, oL1;
    {
        float op0 = o_param[kp * DIM + d];
        float op1 = o_param[(kp + 1) * DIM + d];
        float ls0 = fminf(op0, 0.0f) - log1pf(expf(-fabsf(op0)));
        float ls1 = fminf(op1, 0.0f) - log1pf(expf(-fabsf(op1)));
        oL0 = expf(ls0 * (INV_TAU * (float)CHUNK));
        oL1 = expf(ls1 * (INV_TAU * (float)CHUNK));
    }

    float s0[NCHUNK], s1[NCHUNK];
    #pragma unroll
    for (int c = 0; c < NCHUNK; c++) {
        s0[c] = g_S[(((size_t)b * NCHUNK + c) * KEXP + kp) * DIM + d];
        s1[c] = g_S[(((size_t)b * NCHUNK + c) * KEXP + kp + 1) * DIM + d];
    }
    float p0 = 0.0f, p1 = 0.0f;
    #pragma unroll
    for (int c = 0; c < NCHUNK; c++) {
        g_P[(((size_t)b * NCHUNK + c) * KEXP + kp) * DIM + d] = p0;
        g_P[(((size_t)b * NCHUNK + c) * KEXP + kp + 1) * DIM + d] = p1;
        p0 = fmaf(oL0, p0, s0[c]);
        p1 = fmaf(oL1, p1, s1[c]);
    }
}

// ---------------------------------------------------------------------------
// Scan phase 3 + LayerNorm fused. Phase1 only writes ybuf; warp w then
// row-reduces timestep w from SMEM. grid (NCHUNK, BATCH), block 512.
// ---------------------------------------------------------------------------
#define TG 16   // timesteps buffered per group

__global__ __launch_bounds__(DIM) void scan_apply_ln_kernel(const float* __restrict__ o_param,
                                                            const float* __restrict__ gamma,
                                                            const float* __restrict__ beta) {
    __shared__ float ybuf[TG][DIM];
    __shared__ float smu[TG], srstd[TG];

    const int c = blockIdx.x, b = blockIdx.y, d = threadIdx.x;
    const int lane = d & 31, warp = d >> 5;

    float o[KEXP], m[KEXP];
    load_decay(o_param, d, INV_TAU, o);
    #pragma unroll
    for (int k = 0; k < KEXP; k++)
        m[k] = g_P[(((size_t)b * NCHUNK + c) * KEXP + k) * DIM + d];

    const float gam = gamma[d];
    const float bet = beta[d];

    const int t0 = c * CHUNK;
    const size_t rowbase = (size_t)b * SEQ + t0;
    const float* ip = g_i + rowbase * DIM + d;
    const float* ep = g_e + rowbase * KEXP;
    const float* sp = g_s + rowbase * KEXP;

    for (int g = 0; g < CHUNK / TG; ++g) {
        #pragma unroll 4
        for (int tt = 0; tt < TG; ++tt) {
            const int t = g * TG + tt;
            float iv = ip[(size_t)t * DIM];
            float4 e0 = *(const float4*)(ep + t * KEXP);
            float4 e1 = *(const float4*)(ep + t * KEXP + 4);
            float4 s0 = *(const float4*)(sp + t * KEXP);
            float4 s1 = *(const float4*)(sp + t * KEXP + 4);
            float ev[KEXP] = {e0.x, e0.y, e0.z, e0.w, e1.x, e1.y, e1.z, e1.w};
            float sv[KEXP] = {s0.x, s0.y, s0.z, s0.w, s1.x, s1.y, s1.z, s1.w};
            float y0 = 0.0f, y1 = 0.0f;
            #pragma unroll
            for (int k = 0; k < KEXP; k += 2) {
                m[k]     = fmaf(o[k],     m[k],     ev[k]     * iv);
                m[k + 1] = fmaf(o[k + 1], m[k + 1], ev[k + 1] * iv);
                y0 = fmaf(sv[k],     m[k],     y0);
                y1 = fmaf(sv[k + 1], m[k + 1], y1);
            }
            ybuf[tt][d] = y0 + y1;
        }
        __syncthreads();

        // warp w reduces timestep tt=w over the full 512-dim row
        {
            float s1r = 0.0f, s2r = 0.0f;
            #pragma unroll
            for (int j = 0; j < 16; ++j) {
                const float v = ybuf[warp][lane + j * 32];
                s1r += v;
                s2r = fmaf(v, v, s2r);
            }
            #pragma unroll
            for (int off = 16; off > 0; off >>= 1) {
                s1r += __shfl_xor_sync(0xFFFFFFFFu, s1r, off);
                s2r += __shfl_xor_sync(0xFFFFFFFFu, s2r, off);
            }
            if (lane == 0) {
                const float mu = s1r * (1.0f / DIM);
                const float var = s2r * (1.0f / DIM) - mu * mu;
                smu[warp] = mu;
                srstd[warp] = rsqrtf(var + LN_EPS);
            }
        }
        __syncthreads();

        #pragma unroll 4
        for (int tt = 0; tt < TG; ++tt) {
            const size_t row = rowbase + g * TG + tt;
            const float rv = fmaf((ybuf[tt][d] - smu[tt]) * srstd[tt], gam, bet);
            __half h, l;
            split_half(rv, h, l);
            g_yhi[row * DIM + d] = h;
            g_ylo[row * DIM + d] = l;
        }
        __syncthreads();
    }
}

// ---------------------------------------------------------------------------
// Launch
// ---------------------------------------------------------------------------
extern "C" void kernel_launch(void* const* d_in, const int* in_sizes, int n_in,
                              void* d_out, int out_size) {
    const float* x       = (const float*)d_in[0];
    const float* W_i     = (const float*)d_in[1];
    const float* W_e     = (const float*)d_in[2];
    const float* W_s     = (const float*)d_in[3];
    const float* o_param = (const float*)d_in[4];
    const float* gamma   = (const float*)d_in[5];
    const float* beta    = (const float*)d_in[6];
    const float* W_out   = (const float*)d_in[7];
    float* out = (float*)d_out;

    cudaFuncSetAttribute(gemm1_kernel,
                         cudaFuncAttributeMaxDynamicSharedMemorySize, GSM_TOTAL);
    cudaFuncSetAttribute(gemm2_kernel,
                         cudaFuncAttributeMaxDynamicSharedMemorySize, GSM_TOTAL);

    convert_x_kernel<<<ROWS * DIM / 4 / 256, 256>>>(x);
    convert_w_kernel<<<dim3(16, 16, 2), dim3(32, 8)>>>(W_i, W_out);
    convert_wes_kernel<<<1, 256>>>(W_e, W_s);
    gemm1_kernel<<<dim3(4, 128), 256, GSM_TOTAL>>>();
    es_mma_kernel<<<128, 128>>>();
    scan_local_kernel<<<dim3(NCHUNK, BATCH), DIM>>>(o_param);
    scan_prefix_kernel<<<dim3(BATCH, KEXP / 2), DIM>>>(o_param);
    scan_apply_ln_kernel<<<dim3(NCHUNK, BATCH), DIM>>>(o_param, gamma, beta);
    gemm2_kernel<<<dim3(4, 128), 256, GSM_TOTAL>>>(out);
}

// round 9
// speedup vs baseline: 1.4638x; 1.4638x over previous
#include <cuda_runtime.h>
#include <cuda_fp16.h>
#include <math.h>
#include <cstdint>

// Problem constants
#define BATCH 4
#define SEQ   4096
#define DIM   512
#define KEXP  8
#define ROWS  (BATCH*SEQ)        // 16384 token rows
#define CHUNK 128                // scan chunk length
#define NCHUNK (SEQ/CHUNK)       // 32 chunks
#define INV_TAU (1.0f/16.0f)
#define LN_EPS 1e-5f

// ---------------------------------------------------------------------------
// Scratch (static device globals)
// ---------------------------------------------------------------------------
__device__ float g_i[ROWS * DIM];                       // x @ W_i (fp32)
__device__ float g_e[ROWS * KEXP];
__device__ float g_s[ROWS * KEXP];
__device__ float g_S[BATCH * NCHUNK * KEXP * DIM];
__device__ float g_P[BATCH * NCHUNK * KEXP * DIM];
__device__ __half g_xh[ROWS * DIM];                     // fp16(x)
__device__ __half g_yh[ROWS * DIM];                     // fp16(LN(y))
__device__ __half g_wi[DIM * DIM];                      // W_i^T  [N,K] fp16
__device__ __half g_wo[DIM * DIM];                      // W_out^T [N,K] fp16
__device__ __half g_wes[16 * DIM];                      // [W_e|W_s]^T [16,K] fp16

// ---------------------------------------------------------------------------
// PTX primitives (baseline sm_80+ — legal for compute_103 PTX target)
// ---------------------------------------------------------------------------
__device__ __forceinline__ uint32_t smem_to_u32(const void* p) {
    uint32_t a;
    asm("{ .reg .u64 t; cvta.to.shared.u64 t, %1; cvt.u32.u64 %0, t; }" : "=r"(a) : "l"(p));
    return a;
}

__device__ __forceinline__ void cp16(uint32_t dst, const void* src) {
    asm volatile("cp.async.cg.shared.global [%0], [%1], 16;" :: "r"(dst), "l"(src));
}
__device__ __forceinline__ void cp_commit() {
    asm volatile("cp.async.commit_group;" ::: "memory");
}
template <int N>
__device__ __forceinline__ void cp_wait() {
    asm volatile("cp.async.wait_group %0;" :: "n"(N) : "memory");
}

__device__ __forceinline__ void ldsm4(uint32_t* r, uint32_t addr) {
    asm volatile("ldmatrix.sync.aligned.m8n8.x4.shared.b16 {%0,%1,%2,%3}, [%4];"
                 : "=r"(r[0]), "=r"(r[1]), "=r"(r[2]), "=r"(r[3]) : "r"(addr));
}

__device__ __forceinline__ void mma16816(float* c, const uint32_t* a, const uint32_t* b) {
    asm volatile(
        "mma.sync.aligned.m16n8k16.row.col.f32.f16.f16.f32 "
        "{%0,%1,%2,%3}, {%4,%5,%6,%7}, {%8,%9}, {%0,%1,%2,%3};"
        : "+f"(c[0]), "+f"(c[1]), "+f"(c[2]), "+f"(c[3])
        : "r"(a[0]), "r"(a[1]), "r"(a[2]), "r"(a[3]), "r"(b[0]), "r"(b[1]));
}

// Swizzle: XOR bits[4:5] with bits[7:8], applied to the FINAL 16B-chunk offset.
// 32B row pitch only; never add offsets after swizzling.
__device__ __forceinline__ uint32_t swz(uint32_t off) {
    return off ^ (((off >> 7) & 3u) << 4);
}

// ---------------------------------------------------------------------------
// HMMA fp16 GEMM: C[Mx512] = A * B^T  (single-term fp16)
// A: fp16 [M,512] row-major; B: fp16 [512,512] = W^T, [N,K] row-major
// CTA tile 128(M)x128(N), BK=16, 8 warps of 32x64 (R6-proven structure).
// 4-stage cp.async ring in 32KB static SMEM, ONE __syncthreads per k-iter.
// ---------------------------------------------------------------------------
#define NKI (DIM/16)             // 32 k-iterations
#define TILE_B 4096              // bytes per tile (128 rows x 32B)
#define GSTAGES 4

struct __align__(128) GemmSmem { char buf[GSTAGES][2][TILE_B]; };  // 32 KB

__device__ __forceinline__ void gemm_load(uint32_t sbase, int stage, int c,
                                          const __half* A, const __half* B,
                                          int row0, int col0, int tid) {
    const int r = tid >> 1;              // 0..127
    const int h = tid & 1;               // 16B half of the 32B row
    const uint32_t soff = swz((uint32_t)(r * 32 + h * 16));
    const size_t ga = (size_t)(row0 + r) * DIM + c * 16 + h * 8;
    const size_t gb = (size_t)(col0 + r) * DIM + c * 16 + h * 8;
    const uint32_t base = sbase + (uint32_t)(stage * 2 * TILE_B);
    cp16(base + 0 * TILE_B + soff, A + ga);
    cp16(base + 1 * TILE_B + soff, B + gb);
}

__device__ __forceinline__ void gemm_body(const __half* __restrict__ A,
                                          const __half* __restrict__ B,
                                          float* __restrict__ C) {
    __shared__ GemmSmem sm;
    const uint32_t sbase = smem_to_u32(&sm);
    const int tid = threadIdx.x;
    const int lane = tid & 31;
    const int wid = tid >> 5;
    const int warp_m = wid >> 1;         // 0..3 -> 32-row slice
    const int warp_n = wid & 1;          // 0..1 -> 64-col slice
    const int row0 = blockIdx.y * 128;
    const int col0 = blockIdx.x * 128;

    const int lr = lane & 15;
    const int lc = (lane >> 4) & 1;

    float acc[2][8][4];
    #pragma unroll
    for (int m = 0; m < 2; m++)
        #pragma unroll
        for (int n = 0; n < 8; n++)
            #pragma unroll
            for (int q = 0; q < 4; q++) acc[m][n][q] = 0.0f;

    // Prologue: fill stages 0..2 (one commit group each)
    #pragma unroll
    for (int s = 0; s < GSTAGES - 1; ++s) {
        gemm_load(sbase, s, s, A, B, row0, col0, tid);
        cp_commit();
    }

    // ldmatrix source addresses (swizzled), loop-invariant
    uint32_t aAddr[2], bAddr[4];
    #pragma unroll
    for (int m = 0; m < 2; m++)
        aAddr[m] = swz((uint32_t)((warp_m * 32 + m * 16 + lr) * 32 + lc * 16));
    #pragma unroll
    for (int q = 0; q < 4; q++)
        bAddr[q] = swz((uint32_t)((warp_n * 64 + q * 16 + lr) * 32 + lc * 16));

    for (int c = 0; c < NKI; ++c) {
        cp_wait<GSTAGES - 2>();          // stage c resident
        __syncthreads();                 // all warps done with stage c-1

        if (c + GSTAGES - 1 < NKI)
            gemm_load(sbase, (c + GSTAGES - 1) & (GSTAGES - 1), c + GSTAGES - 1,
                      A, B, row0, col0, tid);
        cp_commit();                     // uniform one group per iter

        const uint32_t bb = sbase + (uint32_t)((c & (GSTAGES - 1)) * 2 * TILE_B);
        uint32_t a[2][4], b[8][2];

        #pragma unroll
        for (int q = 0; q < 4; q++) {
            uint32_t t4[4];
            ldsm4(t4, bb + 1 * TILE_B + bAddr[q]);
            b[2*q][0] = t4[0]; b[2*q+1][0] = t4[1];
            b[2*q][1] = t4[2]; b[2*q+1][1] = t4[3];
        }
        ldsm4(a[0], bb + aAddr[0]);
        ldsm4(a[1], bb + aAddr[1]);
        #pragma unroll
        for (int m = 0; m < 2; m++)
            #pragma unroll
            for (int n = 0; n < 8; n++) mma16816(acc[m][n], a[m], b[n]);
    }

    // Epilogue
    const int tr = lane >> 2;
    const int tc = (lane & 3) * 2;
    #pragma unroll
    for (int m = 0; m < 2; m++) {
        const int rbase = row0 + warp_m * 32 + m * 16 + tr;
        #pragma unroll
        for (int n = 0; n < 8; n++) {
            const int col = col0 + warp_n * 64 + n * 8 + tc;
            float* p0 = C + (size_t)rbase * DIM + col;
            float* p1 = C + (size_t)(rbase + 8) * DIM + col;
            *(float2*)p0 = make_float2(acc[m][n][0], acc[m][n][1]);
            *(float2*)p1 = make_float2(acc[m][n][2], acc[m][n][3]);
        }
    }
}

__global__ __launch_bounds__(256, 2) void gemm1_kernel() {
    gemm_body(g_xh, g_wi, g_i);
}
__global__ __launch_bounds__(256, 2) void gemm2_kernel(float* __restrict__ out) {
    gemm_body(g_yh, g_wo, out);
}

// ---------------------------------------------------------------------------
// es via HMMA: [e|s][Mx16] = xh * Wes^T.  Wes^T fp16 [16,512] in SMEM.
// CTA: 128 threads (4 warps), 128 rows. 3-stage ring, single term.
// ES_PITCH in HALVES (>512): 520 -> 1040B/row, bank-skewed.
// ---------------------------------------------------------------------------
#define ES_PITCH 520
#define ESTAGES 3
#define ENKI 32

struct __align__(128) EsSmem {
    char abuf[ESTAGES][TILE_B];      // 12 KB
    __half w[16 * ES_PITCH];         // 16640 B
};

__device__ __forceinline__ void es_load(uint32_t sbase, int stage, int c,
                                        int row0, int r) {
    #pragma unroll
    for (int h = 0; h < 2; ++h) {
        cp16(sbase + (uint32_t)(stage * TILE_B)
                   + swz((uint32_t)(r * 32 + h * 16)),
             g_xh + (size_t)(row0 + r) * DIM + c * 16 + h * 8);
    }
}

__global__ __launch_bounds__(128, 4) void es_mma_kernel() {
    __shared__ EsSmem sm;
    const uint32_t sbase = smem_to_u32(&sm);
    const uint32_t wbase = smem_to_u32(sm.w);
    const int tid = threadIdx.x;
    const int lane = tid & 31;
    const int wid = tid >> 5;            // 0..3
    const int row0 = blockIdx.x * 128;
    const int r = tid;

    // Fill W smem: 16 rows x 512 halves, pitch ES_PITCH halves
    {
        const int row = tid >> 3;              // 0..15
        const int colb = (tid & 7) * 64;       // 0..448
        #pragma unroll
        for (int q = 0; q < 8; ++q) {
            uint4 v = *(const uint4*)(g_wes + row * DIM + colb + q * 8);
            *(uint4*)(sm.w + row * ES_PITCH + colb + q * 8) = v;
        }
    }

    #pragma unroll
    for (int s = 0; s < ESTAGES - 1; ++s) {
        es_load(sbase, s, s, row0, r);
        cp_commit();
    }

    const int lr = lane & 15;
    const int lc = (lane >> 4) & 1;
    uint32_t aAddr[2];
    #pragma unroll
    for (int m = 0; m < 2; m++)
        aAddr[m] = swz((uint32_t)((wid * 32 + m * 16 + lr) * 32 + lc * 16));

    float acc[2][2][4];
    #pragma unroll
    for (int m = 0; m < 2; m++)
        #pragma unroll
        for (int n = 0; n < 2; n++)
            #pragma unroll
            for (int q = 0; q < 4; q++) acc[m][n][q] = 0.0f;

    for (int c = 0; c < ENKI; ++c) {
        cp_wait<ESTAGES - 2>();
        __syncthreads();                 // also covers initial W-fill visibility

        if (c + ESTAGES - 1 < ENKI) {
            int st = (c + ESTAGES - 1) % ESTAGES;
            es_load(sbase, st, c + ESTAGES - 1, row0, r);
        }
        cp_commit();

        uint32_t b[2][2];
        #pragma unroll
        for (int nt = 0; nt < 2; ++nt) {
            const uint32_t base = wbase
                + (uint32_t)(((nt * 8 + (lane >> 2)) * ES_PITCH + c * 16 + (lane & 3) * 2) * 2);
            asm volatile("ld.shared.b32 %0, [%1];" : "=r"(b[nt][0]) : "r"(base));
            asm volatile("ld.shared.b32 %0, [%1];" : "=r"(b[nt][1]) : "r"(base + 16));
        }

        const uint32_t ab = sbase + (uint32_t)((c % ESTAGES) * TILE_B);
        uint32_t a[4];
        #pragma unroll
        for (int m = 0; m < 2; m++) {
            ldsm4(a, ab + aAddr[m]);
            mma16816(acc[m][0], a, b[0]);
            mma16816(acc[m][1], a, b[1]);
        }
    }

    const int tr = lane >> 2;
    const int tc = (lane & 3) * 2;
    #pragma unroll
    for (int m = 0; m < 2; m++) {
        const int rbase = row0 + wid * 32 + m * 16 + tr;
        #pragma unroll
        for (int nt = 0; nt < 2; nt++) {
            float* dst = nt ? g_s : g_e;
            *(float2*)(dst + (size_t)rbase * KEXP + tc) =
                make_float2(acc[m][nt][0], acc[m][nt][1]);
            *(float2*)(dst + (size_t)(rbase + 8) * KEXP + tc) =
                make_float2(acc[m][nt][2], acc[m][nt][3]);
        }
    }
}

// ---------------------------------------------------------------------------
// Conversions
// ---------------------------------------------------------------------------
__global__ __launch_bounds__(256) void convert_x_kernel(const float* __restrict__ x) {
    const size_t i = (size_t)blockIdx.x * 256 + threadIdx.x;   // float4 index
    float4 v = ((const float4*)x)[i];
    __half h[4];
    h[0] = __float2half(v.x);
    h[1] = __float2half(v.y);
    h[2] = __float2half(v.z);
    h[3] = __float2half(v.w);
    ((uint2*)g_xh)[i] = *(uint2*)h;
}

__global__ __launch_bounds__(256) void convert_w_kernel(const float* __restrict__ W_i,
                                                        const float* __restrict__ W_out) {
    __shared__ float t[32][33];
    const int z = blockIdx.z;
    const float* W = z ? W_out : W_i;
    __half* D = z ? g_wo : g_wi;
    const int n0 = blockIdx.x * 32, k0 = blockIdx.y * 32;
    const int tx = threadIdx.x, ty = threadIdx.y;
    #pragma unroll
    for (int j = 0; j < 4; ++j)
        t[ty + j * 8][tx] = W[(size_t)(k0 + ty + j * 8) * DIM + n0 + tx];
    __syncthreads();
    #pragma unroll
    for (int j = 0; j < 4; ++j) {
        const int nn = ty + j * 8;
        D[(size_t)(n0 + nn) * DIM + k0 + tx] = __float2half(t[tx][nn]);
    }
}

__global__ __launch_bounds__(256) void convert_wes_kernel(const float* __restrict__ W_e,
                                                          const float* __restrict__ W_s) {
    for (int e = threadIdx.x; e < 16 * DIM; e += 256) {
        const int j = e >> 9, d = e & 511;
        const float v = (j < 8) ? W_e[d * KEXP + j] : W_s[d * KEXP + j - 8];
        g_wes[e] = __float2half(v);
    }
}

// ---------------------------------------------------------------------------
// Decay helper
// ---------------------------------------------------------------------------
__device__ __forceinline__ void load_decay(const float* __restrict__ o_param,
                                           int d, float scale, float o[KEXP]) {
    #pragma unroll
    for (int k = 0; k < KEXP; k++) {
        float op = o_param[k * DIM + d];
        float ls = fminf(op, 0.0f) - log1pf(expf(-fabsf(op)));
        o[k] = expf(ls * scale);
    }
}

// ---------------------------------------------------------------------------
// Scan phase 1: per-chunk local end state
// ---------------------------------------------------------------------------
__global__ __launch_bounds__(DIM) void scan_local_kernel(const float* __restrict__ o_param) {
    const int c = blockIdx.x, b = blockIdx.y, d = threadIdx.x;
    float o[KEXP], m[KEXP];
    load_decay(o_param, d, INV_TAU, o);
    #pragma unroll
    for (int k = 0; k < KEXP; k++) m[k] = 0.0f;

    const int t0 = c * CHUNK;
    const float* ip = g_i + ((size_t)b * SEQ + t0) * DIM + d;
    const float* ep = g_e + ((size_t)b * SEQ + t0) * KEXP;

    #pragma unroll 2
    for (int t = 0; t < CHUNK; t++) {
        float iv = ip[(size_t)t * DIM];
        float4 e0 = *(const float4*)(ep + t * KEXP);
        float4 e1 = *(const float4*)(ep + t * KEXP + 4);
        float ev[KEXP] = {e0.x, e0.y, e0.z, e0.w, e1.x, e1.y, e1.z, e1.w};
        #pragma unroll
        for (int k = 0; k < KEXP; k++)
            m[k] = fmaf(o[k], m[k], ev[k] * iv);
    }
    #pragma unroll
    for (int k = 0; k < KEXP; k++)
        g_S[(((size_t)b * NCHUNK + c) * KEXP + k) * DIM + d] = m[k];
}

// ---------------------------------------------------------------------------
// Scan phase 2: prefix over chunks; loads hoisted for MLP.
// ---------------------------------------------------------------------------
__global__ __launch_bounds__(DIM) void scan_prefix_kernel(const float* __restrict__ o_param) {
    const int b = blockIdx.x;
    const int kp = blockIdx.y * 2;
    const int d = threadIdx.x;

    float oL0, oL1;
    {
        float op0 = o_param[kp * DIM + d];
        float op1 = o_param[(kp + 1) * DIM + d];
        float ls0 = fminf(op0, 0.0f) - log1pf(expf(-fabsf(op0)));
        float ls1 = fminf(op1, 0.0f) - log1pf(expf(-fabsf(op1)));
        oL0 = expf(ls0 * (INV_TAU * (float)CHUNK));
        oL1 = expf(ls1 * (INV_TAU * (float)CHUNK));
    }

    float s0[NCHUNK], s1[NCHUNK];
    #pragma unroll
    for (int c = 0; c < NCHUNK; c++) {
        s0[c] = g_S[(((size_t)b * NCHUNK + c) * KEXP + kp) * DIM + d];
        s1[c] = g_S[(((size_t)b * NCHUNK + c) * KEXP + kp + 1) * DIM + d];
    }
    float p0 = 0.0f, p1 = 0.0f;
    #pragma unroll
    for (int c = 0; c < NCHUNK; c++) {
        g_P[(((size_t)b * NCHUNK + c) * KEXP + kp) * DIM + d] = p0;
        g_P[(((size_t)b * NCHUNK + c) * KEXP + kp + 1) * DIM + d] = p1;
        p0 = fmaf(oL0, p0, s0[c]);
        p1 = fmaf(oL1, p1, s1[c]);
    }
}

// ---------------------------------------------------------------------------
// Scan phase 3 + LayerNorm fused. Phase1 only writes ybuf; warp w then
// row-reduces timestep w from SMEM. grid (NCHUNK, BATCH), block 512.
// ---------------------------------------------------------------------------
#define TG 16   // timesteps buffered per group

__global__ __launch_bounds__(DIM) void scan_apply_ln_kernel(const float* __restrict__ o_param,
                                                            const float* __restrict__ gamma,
                                                            const float* __restrict__ beta) {
    __shared__ float ybuf[TG][DIM];
    __shared__ float smu[TG], srstd[TG];

    const int c = blockIdx.x, b = blockIdx.y, d = threadIdx.x;
    const int lane = d & 31, warp = d >> 5;

    float o[KEXP], m[KEXP];
    load_decay(o_param, d, INV_TAU, o);
    #pragma unroll
    for (int k = 0; k < KEXP; k++)
        m[k] = g_P[(((size_t)b * NCHUNK + c) * KEXP + k) * DIM + d];

    const float gam = gamma[d];
    const float bet = beta[d];

    const int t0 = c * CHUNK;
    const size_t rowbase = (size_t)b * SEQ + t0;
    const float* ip = g_i + rowbase * DIM + d;
    const float* ep = g_e + rowbase * KEXP;
    const float* sp = g_s + rowbase * KEXP;

    for (int g = 0; g < CHUNK / TG; ++g) {
        #pragma unroll 4
        for (int tt = 0; tt < TG; ++tt) {
            const int t = g * TG + tt;
            float iv = ip[(size_t)t * DIM];
            float4 e0 = *(const float4*)(ep + t * KEXP);
            float4 e1 = *(const float4*)(ep + t * KEXP + 4);
            float4 s0 = *(const float4*)(sp + t * KEXP);
            float4 s1 = *(const float4*)(sp + t * KEXP + 4);
            float ev[KEXP] = {e0.x, e0.y, e0.z, e0.w, e1.x, e1.y, e1.z, e1.w};
            float sv[KEXP] = {s0.x, s0.y, s0.z, s0.w, s1.x, s1.y, s1.z, s1.w};
            float y0 = 0.0f, y1 = 0.0f;
            #pragma unroll
            for (int k = 0; k < KEXP; k += 2) {
                m[k]     = fmaf(o[k],     m[k],     ev[k]     * iv);
                m[k + 1] = fmaf(o[k + 1], m[k + 1], ev[k + 1] * iv);
                y0 = fmaf(sv[k],     m[k],     y0);
                y1 = fmaf(sv[k + 1], m[k + 1], y1);
            }
            ybuf[tt][d] = y0 + y1;
        }
        __syncthreads();

        // warp w reduces timestep tt=w over the full 512-dim row
        {
            float s1r = 0.0f, s2r = 0.0f;
            #pragma unroll
            for (int j = 0; j < 16; ++j) {
                const float v = ybuf[warp][lane + j * 32];
                s1r += v;
                s2r = fmaf(v, v, s2r);
            }
            #pragma unroll
            for (int off = 16; off > 0; off >>= 1) {
                s1r += __shfl_xor_sync(0xFFFFFFFFu, s1r, off);
                s2r += __shfl_xor_sync(0xFFFFFFFFu, s2r, off);
            }
            if (lane == 0) {
                const float mu = s1r * (1.0f / DIM);
                const float var = s2r * (1.0f / DIM) - mu * mu;
                smu[warp] = mu;
                srstd[warp] = rsqrtf(var + LN_EPS);
            }
        }
        __syncthreads();

        #pragma unroll 4
        for (int tt = 0; tt < TG; ++tt) {
            const size_t row = rowbase + g * TG + tt;
            const float rv = fmaf((ybuf[tt][d] - smu[tt]) * srstd[tt], gam, bet);
            g_yh[row * DIM + d] = __float2half(rv);
        }
        __syncthreads();
    }
}

// ---------------------------------------------------------------------------
// Launch
// ---------------------------------------------------------------------------
extern "C" void kernel_launch(void* const* d_in, const int* in_sizes, int n_in,
                              void* d_out, int out_size) {
    const float* x       = (const float*)d_in[0];
    const float* W_i     = (const float*)d_in[1];
    const float* W_e     = (const float*)d_in[2];
    const float* W_s     = (const float*)d_in[3];
    const float* o_param = (const float*)d_in[4];
    const float* gamma   = (const float*)d_in[5];
    const float* beta    = (const float*)d_in[6];
    const float* W_out   = (const float*)d_in[7];
    float* out = (float*)d_out;

    convert_x_kernel<<<ROWS * DIM / 4 / 256, 256>>>(x);
    convert_w_kernel<<<dim3(16, 16, 2), dim3(32, 8)>>>(W_i, W_out);
    convert_wes_kernel<<<1, 256>>>(W_e, W_s);
    gemm1_kernel<<<dim3(4, 128), 256>>>();
    es_mma_kernel<<<128, 128>>>();
    scan_local_kernel<<<dim3(NCHUNK, BATCH), DIM>>>(o_param);
    scan_prefix_kernel<<<dim3(BATCH, KEXP / 2), DIM>>>(o_param);
    scan_apply_ln_kernel<<<dim3(NCHUNK, BATCH), DIM>>>(o_param, gamma, beta);
    gemm2_kernel<<<dim3(4, 128), 256>>>(out);
}

// round 10
// speedup vs baseline: 1.4744x; 1.0073x over previous
#include <cuda_runtime.h>
#include <cuda_fp16.h>
#include <math.h>
#include <cstdint>

// Problem constants
#define BATCH 4
#define SEQ   4096
#define DIM   512
#define KEXP  8
#define ROWS  (BATCH*SEQ)        // 16384 token rows
#define CHUNK 128                // scan chunk length
#define NCHUNK (SEQ/CHUNK)       // 32 chunks
#define INV_TAU (1.0f/16.0f)
#define LN_EPS 1e-5f

// ---------------------------------------------------------------------------
// Scratch (static device globals)
// ---------------------------------------------------------------------------
__device__ float g_i[ROWS * DIM];                       // x @ W_i (fp32)
__device__ float g_e[ROWS * KEXP];
__device__ float g_s[ROWS * KEXP];
__device__ float g_S[BATCH * NCHUNK * KEXP * DIM];
__device__ float g_P[BATCH * NCHUNK * KEXP * DIM];
__device__ __half g_xh[ROWS * DIM];                     // fp16(x)
__device__ __half g_yh[ROWS * DIM];                     // fp16(LN(y))
__device__ __half g_wi[DIM * DIM];                      // W_i^T  [N,K] fp16
__device__ __half g_wo[DIM * DIM];                      // W_out^T [N,K] fp16
__device__ __half g_wes[16 * DIM];                      // [W_e|W_s]^T [16,K] fp16

// ---------------------------------------------------------------------------
// PTX primitives (baseline sm_80+ — legal for compute_103 PTX target)
// ---------------------------------------------------------------------------
__device__ __forceinline__ uint32_t smem_to_u32(const void* p) {
    uint32_t a;
    asm("{ .reg .u64 t; cvta.to.shared.u64 t, %1; cvt.u32.u64 %0, t; }" : "=r"(a) : "l"(p));
    return a;
}

__device__ __forceinline__ void cp16(uint32_t dst, const void* src) {
    asm volatile("cp.async.cg.shared.global [%0], [%1], 16;" :: "r"(dst), "l"(src));
}
__device__ __forceinline__ void cp_commit() {
    asm volatile("cp.async.commit_group;" ::: "memory");
}
template <int N>
__device__ __forceinline__ void cp_wait() {
    asm volatile("cp.async.wait_group %0;" :: "n"(N) : "memory");
}

__device__ __forceinline__ void ldsm4(uint32_t* r, uint32_t addr) {
    asm volatile("ldmatrix.sync.aligned.m8n8.x4.shared.b16 {%0,%1,%2,%3}, [%4];"
                 : "=r"(r[0]), "=r"(r[1]), "=r"(r[2]), "=r"(r[3]) : "r"(addr));
}

__device__ __forceinline__ void mma16816(float* c, const uint32_t* a, const uint32_t* b) {
    asm volatile(
        "mma.sync.aligned.m16n8k16.row.col.f32.f16.f16.f32 "
        "{%0,%1,%2,%3}, {%4,%5,%6,%7}, {%8,%9}, {%0,%1,%2,%3};"
        : "+f"(c[0]), "+f"(c[1]), "+f"(c[2]), "+f"(c[3])
        : "r"(a[0]), "r"(a[1]), "r"(a[2]), "r"(a[3]), "r"(b[0]), "r"(b[1]));
}

// Swizzle: XOR bits[4:5] with bits[7:8], applied to the FINAL 16B-chunk offset.
// Never add offsets after swizzling — carry corrupts the row index.
__device__ __forceinline__ uint32_t swz(uint32_t off) {
    return off ^ (((off >> 7) & 3u) << 4);
}

// ---------------------------------------------------------------------------
// HMMA fp16 GEMM: C[Mx512] = A * B^T  (single-term fp16)
// CTA tile 128(M)x128(N), 8 warps of 32x64 (R9-proven warp mapping).
// BK=32 per stage (two k16 sub-steps), 3 stages x 16KB = 48KB static SMEM.
// ONE __syncthreads per 32-deep k-step (16 barriers total).
// ---------------------------------------------------------------------------
#define BK 32
#define NKI (DIM/BK)             // 16 k-iterations
#define GTILE_B 8192             // bytes per tile (128 rows x 64B)
#define GSTAGES 3

struct __align__(128) GemmSmem { char buf[GSTAGES][2][GTILE_B]; };  // 48 KB

__device__ __forceinline__ void gemm_load(uint32_t sbase, int stage, int c,
                                          const __half* A, const __half* B,
                                          int row0, int col0, int tid) {
    const int r = tid >> 1;              // 0..127
    const int h = tid & 1;               // 32B half of the 64B row
    const uint32_t so0 = swz((uint32_t)(r * 64 + h * 32));
    const uint32_t so1 = swz((uint32_t)(r * 64 + h * 32 + 16));
    const size_t ga = (size_t)(row0 + r) * DIM + c * BK + h * 16;
    const size_t gb = (size_t)(col0 + r) * DIM + c * BK + h * 16;
    const uint32_t base = sbase + (uint32_t)(stage * 2 * GTILE_B);
    cp16(base + 0 * GTILE_B + so0, A + ga);
    cp16(base + 0 * GTILE_B + so1, A + ga + 8);
    cp16(base + 1 * GTILE_B + so0, B + gb);
    cp16(base + 1 * GTILE_B + so1, B + gb + 8);
}

__device__ __forceinline__ void gemm_body(const __half* __restrict__ A,
                                          const __half* __restrict__ B,
                                          float* __restrict__ C) {
    __shared__ GemmSmem sm;
    const uint32_t sbase = smem_to_u32(&sm);
    const int tid = threadIdx.x;
    const int lane = tid & 31;
    const int wid = tid >> 5;
    const int warp_m = wid >> 1;         // 0..3 -> 32-row slice
    const int warp_n = wid & 1;          // 0..1 -> 64-col slice
    const int row0 = blockIdx.y * 128;
    const int col0 = blockIdx.x * 128;

    const int lr = lane & 15;
    const int lc = (lane >> 4) & 1;

    float acc[2][8][4];
    #pragma unroll
    for (int m = 0; m < 2; m++)
        #pragma unroll
        for (int n = 0; n < 8; n++)
            #pragma unroll
            for (int q = 0; q < 4; q++) acc[m][n][q] = 0.0f;

    // Prologue: fill stages 0..1
    #pragma unroll
    for (int s = 0; s < GSTAGES - 1; ++s) {
        gemm_load(sbase, s, s, A, B, row0, col0, tid);
        cp_commit();
    }

    // ldmatrix addresses: swizzle applied LAST, per (tile-row, k16 sub-step)
    uint32_t aAddr[2][2], bAddr[4][2];
    #pragma unroll
    for (int m = 0; m < 2; m++)
        #pragma unroll
        for (int kk = 0; kk < 2; kk++)
            aAddr[m][kk] = swz((uint32_t)((warp_m * 32 + m * 16 + lr) * 64
                                          + lc * 16 + kk * 32));
    #pragma unroll
    for (int q = 0; q < 4; q++)
        #pragma unroll
        for (int kk = 0; kk < 2; kk++)
            bAddr[q][kk] = swz((uint32_t)((warp_n * 64 + q * 16 + lr) * 64
                                          + lc * 16 + kk * 32));

    for (int c = 0; c < NKI; ++c) {
        cp_wait<GSTAGES - 2>();          // stage c resident
        __syncthreads();                 // all warps done with stage c-1

        if (c + GSTAGES - 1 < NKI)
            gemm_load(sbase, (c + GSTAGES - 1) % GSTAGES, c + GSTAGES - 1,
                      A, B, row0, col0, tid);
        cp_commit();                     // uniform one group per iter

        const uint32_t bb = sbase + (uint32_t)((c % GSTAGES) * 2 * GTILE_B);

        #pragma unroll
        for (int kk = 0; kk < 2; ++kk) {
            uint32_t a[2][4], b[8][2];

            #pragma unroll
            for (int q = 0; q < 4; q++) {
                uint32_t t4[4];
                ldsm4(t4, bb + 1 * GTILE_B + bAddr[q][kk]);
                b[2*q][0] = t4[0]; b[2*q+1][0] = t4[1];
                b[2*q][1] = t4[2]; b[2*q+1][1] = t4[3];
            }
            ldsm4(a[0], bb + aAddr[0][kk]);
            ldsm4(a[1], bb + aAddr[1][kk]);
            #pragma unroll
            for (int m = 0; m < 2; m++)
                #pragma unroll
                for (int n = 0; n < 8; n++) mma16816(acc[m][n], a[m], b[n]);
        }
    }

    // Epilogue
    const int tr = lane >> 2;
    const int tc = (lane & 3) * 2;
    #pragma unroll
    for (int m = 0; m < 2; m++) {
        const int rbase = row0 + warp_m * 32 + m * 16 + tr;
        #pragma unroll
        for (int n = 0; n < 8; n++) {
            const int col = col0 + warp_n * 64 + n * 8 + tc;
            float* p0 = C + (size_t)rbase * DIM + col;
            float* p1 = C + (size_t)(rbase + 8) * DIM + col;
            *(float2*)p0 = make_float2(acc[m][n][0], acc[m][n][1]);
            *(float2*)p1 = make_float2(acc[m][n][2], acc[m][n][3]);
        }
    }
}

__global__ __launch_bounds__(256, 2) void gemm1_kernel() {
    gemm_body(g_xh, g_wi, g_i);
}
__global__ __launch_bounds__(256, 2) void gemm2_kernel(float* __restrict__ out) {
    gemm_body(g_yh, g_wo, out);
}

// ---------------------------------------------------------------------------
// es via HMMA: [e|s][Mx16] = xh * Wes^T (unchanged from R9)
// ---------------------------------------------------------------------------
#define ETILE_B 4096             // 128 rows x 32B
#define ES_PITCH 520
#define ESTAGES 3
#define ENKI 32

struct __align__(128) EsSmem {
    char abuf[ESTAGES][ETILE_B];     // 12 KB
    __half w[16 * ES_PITCH];         // 16640 B
};

__device__ __forceinline__ void es_load(uint32_t sbase, int stage, int c,
                                        int row0, int r) {
    #pragma unroll
    for (int h = 0; h < 2; ++h) {
        cp16(sbase + (uint32_t)(stage * ETILE_B)
                   + swz((uint32_t)(r * 32 + h * 16)),
             g_xh + (size_t)(row0 + r) * DIM + c * 16 + h * 8);
    }
}

__global__ __launch_bounds__(128, 4) void es_mma_kernel() {
    __shared__ EsSmem sm;
    const uint32_t sbase = smem_to_u32(&sm);
    const uint32_t wbase = smem_to_u32(sm.w);
    const int tid = threadIdx.x;
    const int lane = tid & 31;
    const int wid = tid >> 5;            // 0..3
    const int row0 = blockIdx.x * 128;
    const int r = tid;

    {
        const int row = tid >> 3;              // 0..15
        const int colb = (tid & 7) * 64;       // 0..448
        #pragma unroll
        for (int q = 0; q < 8; ++q) {
            uint4 v = *(const uint4*)(g_wes + row * DIM + colb + q * 8);
            *(uint4*)(sm.w + row * ES_PITCH + colb + q * 8) = v;
        }
    }

    #pragma unroll
    for (int s = 0; s < ESTAGES - 1; ++s) {
        es_load(sbase, s, s, row0, r);
        cp_commit();
    }

    const int lr = lane & 15;
    const int lc = (lane >> 4) & 1;
    uint32_t aAddr[2];
    #pragma unroll
    for (int m = 0; m < 2; m++)
        aAddr[m] = swz((uint32_t)((wid * 32 + m * 16 + lr) * 32 + lc * 16));

    float acc[2][2][4];
    #pragma unroll
    for (int m = 0; m < 2; m++)
        #pragma unroll
        for (int n = 0; n < 2; n++)
            #pragma unroll
            for (int q = 0; q < 4; q++) acc[m][n][q] = 0.0f;

    for (int c = 0; c < ENKI; ++c) {
        cp_wait<ESTAGES - 2>();
        __syncthreads();

        if (c + ESTAGES - 1 < ENKI) {
            int st = (c + ESTAGES - 1) % ESTAGES;
            es_load(sbase, st, c + ESTAGES - 1, row0, r);
        }
        cp_commit();

        uint32_t b[2][2];
        #pragma unroll
        for (int nt = 0; nt < 2; ++nt) {
            const uint32_t base = wbase
                + (uint32_t)(((nt * 8 + (lane >> 2)) * ES_PITCH + c * 16 + (lane & 3) * 2) * 2);
            asm volatile("ld.shared.b32 %0, [%1];" : "=r"(b[nt][0]) : "r"(base));
            asm volatile("ld.shared.b32 %0, [%1];" : "=r"(b[nt][1]) : "r"(base + 16));
        }

        const uint32_t ab = sbase + (uint32_t)((c % ESTAGES) * ETILE_B);
        uint32_t a[4];
        #pragma unroll
        for (int m = 0; m < 2; m++) {
            ldsm4(a, ab + aAddr[m]);
            mma16816(acc[m][0], a, b[0]);
            mma16816(acc[m][1], a, b[1]);
        }
    }

    const int tr = lane >> 2;
    const int tc = (lane & 3) * 2;
    #pragma unroll
    for (int m = 0; m < 2; m++) {
        const int rbase = row0 + wid * 32 + m * 16 + tr;
        #pragma unroll
        for (int nt = 0; nt < 2; nt++) {
            float* dst = nt ? g_s : g_e;
            *(float2*)(dst + (size_t)rbase * KEXP + tc) =
                make_float2(acc[m][nt][0], acc[m][nt][1]);
            *(float2*)(dst + (size_t)(rbase + 8) * KEXP + tc) =
                make_float2(acc[m][nt][2], acc[m][nt][3]);
        }
    }
}

// ---------------------------------------------------------------------------
// Fused conversions: one launch.
//   blocks [0, 8192)         : x -> fp16
//   blocks [8192, 8704)      : W_i / W_out transpose -> fp16
//   block  8704              : W_e|W_s -> fp16
// ---------------------------------------------------------------------------
#define CVT_XBLOCKS (ROWS * DIM / 4 / 256)   // 8192

__global__ __launch_bounds__(256) void convert_all_kernel(
        const float* __restrict__ x,
        const float* __restrict__ W_i, const float* __restrict__ W_out,
        const float* __restrict__ W_e, const float* __restrict__ W_s) {
    __shared__ float t[32][33];
    const int bid = blockIdx.x;
    const int tid = threadIdx.x;

    if (bid < CVT_XBLOCKS) {
        const size_t i = (size_t)bid * 256 + tid;   // float4 index
        float4 v = ((const float4*)x)[i];
        __half h[4];
        h[0] = __float2half(v.x);
        h[1] = __float2half(v.y);
        h[2] = __float2half(v.z);
        h[3] = __float2half(v.w);
        ((uint2*)g_xh)[i] = *(uint2*)h;
    } else if (bid < CVT_XBLOCKS + 512) {
        const int idx = bid - CVT_XBLOCKS;          // 0..511
        const int z = idx >> 8;                      // 0..1
        const float* W = z ? W_out : W_i;
        __half* D = z ? g_wo : g_wi;
        const int n0 = (idx & 15) * 32;
        const int k0 = ((idx >> 4) & 15) * 32;
        const int tx = tid & 31, ty = tid >> 5;      // 32 x 8
        #pragma unroll
        for (int j = 0; j < 4; ++j)
            t[ty + j * 8][tx] = W[(size_t)(k0 + ty + j * 8) * DIM + n0 + tx];
        __syncthreads();
        #pragma unroll
        for (int j = 0; j < 4; ++j) {
            const int nn = ty + j * 8;
            D[(size_t)(n0 + nn) * DIM + k0 + tx] = __float2half(t[tx][nn]);
        }
    } else {
        for (int e = tid; e < 16 * DIM; e += 256) {
            const int j = e >> 9, d = e & 511;
            const float v = (j < 8) ? W_e[d * KEXP + j] : W_s[d * KEXP + j - 8];
            g_wes[e] = __float2half(v);
        }
    }
}

// ---------------------------------------------------------------------------
// Decay helper
// ---------------------------------------------------------------------------
__device__ __forceinline__ void load_decay(const float* __restrict__ o_param,
                                           int d, float scale, float o[KEXP]) {
    #pragma unroll
    for (int k = 0; k < KEXP; k++) {
        float op = o_param[k * DIM + d];
        float ls = fminf(op, 0.0f) - log1pf(expf(-fabsf(op)));
        o[k] = expf(ls * scale);
    }
}

// ---------------------------------------------------------------------------
// Scan phase 1: per-chunk local end state
// ---------------------------------------------------------------------------
__global__ __launch_bounds__(DIM) void scan_local_kernel(const float* __restrict__ o_param) {
    const int c = blockIdx.x, b = blockIdx.y, d = threadIdx.x;
    float o[KEXP], m[KEXP];
    load_decay(o_param, d, INV_TAU, o);
    #pragma unroll
    for (int k = 0; k < KEXP; k++) m[k] = 0.0f;

    const int t0 = c * CHUNK;
    const float* ip = g_i + ((size_t)b * SEQ + t0) * DIM + d;
    const float* ep = g_e + ((size_t)b * SEQ + t0) * KEXP;

    #pragma unroll 2
    for (int t = 0; t < CHUNK; t++) {
        float iv = ip[(size_t)t * DIM];
        float4 e0 = *(const float4*)(ep + t * KEXP);
        float4 e1 = *(const float4*)(ep + t * KEXP + 4);
        float ev[KEXP] = {e0.x, e0.y, e0.z, e0.w, e1.x, e1.y, e1.z, e1.w};
        #pragma unroll
        for (int k = 0; k < KEXP; k++)
            m[k] = fmaf(o[k], m[k], ev[k] * iv);
    }
    #pragma unroll
    for (int k = 0; k < KEXP; k++)
        g_S[(((size_t)b * NCHUNK + c) * KEXP + k) * DIM + d] = m[k];
}

// ---------------------------------------------------------------------------
// Scan phase 2: prefix over chunks; loads hoisted for MLP.
// ---------------------------------------------------------------------------
__global__ __launch_bounds__(DIM) void scan_prefix_kernel(const float* __restrict__ o_param) {
    const int b = blockIdx.x;
    const int kp = blockIdx.y * 2;
    const int d = threadIdx.x;

    float oL0, oL1;
    {
        float op0 = o_param[kp * DIM + d];
        float op1 = o_param[(kp + 1) * DIM + d];
        float ls0 = fminf(op0, 0.0f) - log1pf(expf(-fabsf(op0)));
        float ls1 = fminf(op1, 0.0f) - log1pf(expf(-fabsf(op1)));
        oL0 = expf(ls0 * (INV_TAU * (float)CHUNK));
        oL1 = expf(ls1 * (INV_TAU * (float)CHUNK));
    }

    float s0[NCHUNK], s1[NCHUNK];
    #pragma unroll
    for (int c = 0; c < NCHUNK; c++) {
        s0[c] = g_S[(((size_t)b * NCHUNK + c) * KEXP + kp) * DIM + d];
        s1[c] = g_S[(((size_t)b * NCHUNK + c) * KEXP + kp + 1) * DIM + d];
    }
    float p0 = 0.0f, p1 = 0.0f;
    #pragma unroll
    for (int c = 0; c < NCHUNK; c++) {
        g_P[(((size_t)b * NCHUNK + c) * KEXP + kp) * DIM + d] = p0;
        g_P[(((size_t)b * NCHUNK + c) * KEXP + kp + 1) * DIM + d] = p1;
        p0 = fmaf(oL0, p0, s0[c]);
        p1 = fmaf(oL1, p1, s1[c]);
    }
}

// ---------------------------------------------------------------------------
// Scan phase 3 + LayerNorm fused. Phase1 only writes ybuf; warp w then
// row-reduces timestep w from SMEM. grid (NCHUNK, BATCH), block 512.
// ---------------------------------------------------------------------------
#define TG 16   // timesteps buffered per group

__global__ __launch_bounds__(DIM) void scan_apply_ln_kernel(const float* __restrict__ o_param,
                                                            const float* __restrict__ gamma,
                                                            const float* __restrict__ beta) {
    __shared__ float ybuf[TG][DIM];
    __shared__ float smu[TG], srstd[TG];

    const int c = blockIdx.x, b = blockIdx.y, d = threadIdx.x;
    const int lane = d & 31, warp = d >> 5;

    float o[KEXP], m[KEXP];
    load_decay(o_param, d, INV_TAU, o);
    #pragma unroll
    for (int k = 0; k < KEXP; k++)
        m[k] = g_P[(((size_t)b * NCHUNK + c) * KEXP + k) * DIM + d];

    const float gam = gamma[d];
    const float bet = beta[d];

    const int t0 = c * CHUNK;
    const size_t rowbase = (size_t)b * SEQ + t0;
    const float* ip = g_i + rowbase * DIM + d;
    const float* ep = g_e + rowbase * KEXP;
    const float* sp = g_s + rowbase * KEXP;

    for (int g = 0; g < CHUNK / TG; ++g) {
        #pragma unroll 4
        for (int tt = 0; tt < TG; ++tt) {
            const int t = g * TG + tt;
            float iv = ip[(size_t)t * DIM];
            float4 e0 = *(const float4*)(ep + t * KEXP);
            float4 e1 = *(const float4*)(ep + t * KEXP + 4);
            float4 s0 = *(const float4*)(sp + t * KEXP);
            float4 s1 = *(const float4*)(sp + t * KEXP + 4);
            float ev[KEXP] = {e0.x, e0.y, e0.z, e0.w, e1.x, e1.y, e1.z, e1.w};
            float sv[KEXP] = {s0.x, s0.y, s0.z, s0.w, s1.x, s1.y, s1.z, s1.w};
            float y0 = 0.0f, y1 = 0.0f;
            #pragma unroll
            for (int k = 0; k < KEXP; k += 2) {
                m[k]     = fmaf(o[k],     m[k],     ev[k]     * iv);
                m[k + 1] = fmaf(o[k + 1], m[k + 1], ev[k + 1] * iv);
                y0 = fmaf(sv[k],     m[k],     y0);
                y1 = fmaf(sv[k + 1], m[k + 1], y1);
            }
            ybuf[tt][d] = y0 + y1;
        }
        __syncthreads();

        // warp w reduces timestep tt=w over the full 512-dim row
        {
            float s1r = 0.0f, s2r = 0.0f;
            #pragma unroll
            for (int j = 0; j < 16; ++j) {
                const float v = ybuf[warp][lane + j * 32];
                s1r += v;
                s2r = fmaf(v, v, s2r);
            }
            #pragma unroll
            for (int off = 16; off > 0; off >>= 1) {
                s1r += __shfl_xor_sync(0xFFFFFFFFu, s1r, off);
                s2r += __shfl_xor_sync(0xFFFFFFFFu, s2r, off);
            }
            if (lane == 0) {
                const float mu = s1r * (1.0f / DIM);
                const float var = s2r * (1.0f / DIM) - mu * mu;
                smu[warp] = mu;
                srstd[warp] = rsqrtf(var + LN_EPS);
            }
        }
        __syncthreads();

        #pragma unroll 4
        for (int tt = 0; tt < TG; ++tt) {
            const size_t row = rowbase + g * TG + tt;
            const float rv = fmaf((ybuf[tt][d] - smu[tt]) * srstd[tt], gam, bet);
            g_yh[row * DIM + d] = __float2half(rv);
        }
        __syncthreads();
    }
}

// ---------------------------------------------------------------------------
// Launch
// ---------------------------------------------------------------------------
extern "C" void kernel_launch(void* const* d_in, const int* in_sizes, int n_in,
                              void* d_out, int out_size) {
    const float* x       = (const float*)d_in[0];
    const float* W_i     = (const float*)d_in[1];
    const float* W_e     = (const float*)d_in[2];
    const float* W_s     = (const float*)d_in[3];
    const float* o_param = (const float*)d_in[4];
    const float* gamma   = (const float*)d_in[5];
    const float* beta    = (const float*)d_in[6];
    const float* W_out   = (const float*)d_in[7];
    float* out = (float*)d_out;

    convert_all_kernel<<<CVT_XBLOCKS + 512 + 1, 256>>>(x, W_i, W_out, W_e, W_s);
    gemm1_kernel<<<dim3(4, 128), 256>>>();
    es_mma_kernel<<<128, 128>>>();
    scan_local_kernel<<<dim3(NCHUNK, BATCH), DIM>>>(o_param);
    scan_prefix_kernel<<<dim3(BATCH, KEXP / 2), DIM>>>(o_param);
    scan_apply_ln_kernel<<<dim3(NCHUNK, BATCH), DIM>>>(o_param, gamma, beta);
    gemm2_kernel<<<dim3(4, 128), 256>>>(out);
}

// round 11
// speedup vs baseline: 1.6391x; 1.1117x over previous
#include <cuda_runtime.h>
#include <cuda_fp16.h>
#include <math.h>
#include <cstdint>

// Problem constants
#define BATCH 4
#define SEQ   4096
#define DIM   512
#define KEXP  8
#define ROWS  (BATCH*SEQ)        // 16384 token rows
#define CHUNK 128                // scan chunk length
#define NCHUNK (SEQ/CHUNK)       // 32 chunks
#define INV_TAU (1.0f/16.0f)
#define LN_EPS 1e-5f

// ---------------------------------------------------------------------------
// Scratch (static device globals)
// ---------------------------------------------------------------------------
__device__ float g_i[ROWS * DIM];                       // x @ W_i (fp32)
__device__ float g_e[ROWS * KEXP];
__device__ float g_s[ROWS * KEXP];
__device__ float g_S[BATCH * NCHUNK * KEXP * DIM];
__device__ float g_P[BATCH * NCHUNK * KEXP * DIM];
__device__ __half g_xh[ROWS * DIM];                     // fp16(x)
__device__ __half g_yh[ROWS * DIM];                     // fp16(LN(y))
__device__ __half g_wi[DIM * DIM];                      // W_i^T  [N,K] fp16
__device__ __half g_wo[DIM * DIM];                      // W_out^T [N,K] fp16
__device__ __half g_wes[16 * DIM];                      // [W_e|W_s]^T [16,K] fp16

// ---------------------------------------------------------------------------
// PTX primitives (baseline sm_80+ — legal for compute_103 PTX target)
// ---------------------------------------------------------------------------
__device__ __forceinline__ uint32_t smem_to_u32(const void* p) {
    uint32_t a;
    asm("{ .reg .u64 t; cvta.to.shared.u64 t, %1; cvt.u32.u64 %0, t; }" : "=r"(a) : "l"(p));
    return a;
}

__device__ __forceinline__ void cp16(uint32_t dst, const void* src) {
    asm volatile("cp.async.cg.shared.global [%0], [%1], 16;" :: "r"(dst), "l"(src));
}
__device__ __forceinline__ void cp_commit() {
    asm volatile("cp.async.commit_group;" ::: "memory");
}
template <int N>
__device__ __forceinline__ void cp_wait() {
    asm volatile("cp.async.wait_group %0;" :: "n"(N) : "memory");
}

__device__ __forceinline__ void ldsm4(uint32_t* r, uint32_t addr) {
    asm volatile("ldmatrix.sync.aligned.m8n8.x4.shared.b16 {%0,%1,%2,%3}, [%4];"
                 : "=r"(r[0]), "=r"(r[1]), "=r"(r[2]), "=r"(r[3]) : "r"(addr));
}

__device__ __forceinline__ void mma16816(float* c, const uint32_t* a, const uint32_t* b) {
    asm volatile(
        "mma.sync.aligned.m16n8k16.row.col.f32.f16.f16.f32 "
        "{%0,%1,%2,%3}, {%4,%5,%6,%7}, {%8,%9}, {%0,%1,%2,%3};"
        : "+f"(c[0]), "+f"(c[1]), "+f"(c[2]), "+f"(c[3])
        : "r"(a[0]), "r"(a[1]), "r"(a[2]), "r"(a[3]), "r"(b[0]), "r"(b[1]));
}

// Swizzle: XOR bits[4:5] with bits[7:8], applied to the FINAL 16B-chunk offset.
// Never add offsets after swizzling — carry corrupts the row index.
__device__ __forceinline__ uint32_t swz(uint32_t off) {
    return off ^ (((off >> 7) & 3u) << 4);
}

// ---------------------------------------------------------------------------
// HMMA fp16 GEMM: C[Mx512] = A * B^T  (single-term fp16)
// CTA tile 128(M)x128(N), 8 warps of 32x64, BK=32 (two k16 sub-steps),
// 3 stages x 16KB = 48KB static SMEM, ONE __syncthreads per 32-deep k-step.
// ---------------------------------------------------------------------------
#define BK 32
#define NKI (DIM/BK)             // 16 k-iterations
#define GTILE_B 8192             // bytes per tile (128 rows x 64B)
#define GSTAGES 3

struct __align__(128) GemmSmem { char buf[GSTAGES][2][GTILE_B]; };  // 48 KB

__device__ __forceinline__ void gemm_load(uint32_t sbase, int stage, int c,
                                          const __half* A, const __half* B,
                                          int row0, int col0, int tid) {
    const int r = tid >> 1;              // 0..127
    const int h = tid & 1;               // 32B half of the 64B row
    const uint32_t so0 = swz((uint32_t)(r * 64 + h * 32));
    const uint32_t so1 = swz((uint32_t)(r * 64 + h * 32 + 16));
    const size_t ga = (size_t)(row0 + r) * DIM + c * BK + h * 16;
    const size_t gb = (size_t)(col0 + r) * DIM + c * BK + h * 16;
    const uint32_t base = sbase + (uint32_t)(stage * 2 * GTILE_B);
    cp16(base + 0 * GTILE_B + so0, A + ga);
    cp16(base + 0 * GTILE_B + so1, A + ga + 8);
    cp16(base + 1 * GTILE_B + so0, B + gb);
    cp16(base + 1 * GTILE_B + so1, B + gb + 8);
}

__device__ __forceinline__ void gemm_body(const __half* __restrict__ A,
                                          const __half* __restrict__ B,
                                          float* __restrict__ C) {
    __shared__ GemmSmem sm;
    const uint32_t sbase = smem_to_u32(&sm);
    const int tid = threadIdx.x;
    const int lane = tid & 31;
    const int wid = tid >> 5;
    const int warp_m = wid >> 1;         // 0..3 -> 32-row slice
    const int warp_n = wid & 1;          // 0..1 -> 64-col slice
    const int row0 = blockIdx.y * 128;
    const int col0 = blockIdx.x * 128;

    const int lr = lane & 15;
    const int lc = (lane >> 4) & 1;

    float acc[2][8][4];
    #pragma unroll
    for (int m = 0; m < 2; m++)
        #pragma unroll
        for (int n = 0; n < 8; n++)
            #pragma unroll
            for (int q = 0; q < 4; q++) acc[m][n][q] = 0.0f;

    // Prologue: fill stages 0..1
    #pragma unroll
    for (int s = 0; s < GSTAGES - 1; ++s) {
        gemm_load(sbase, s, s, A, B, row0, col0, tid);
        cp_commit();
    }

    // ldmatrix addresses: swizzle applied LAST, per (tile-row, k16 sub-step)
    uint32_t aAddr[2][2], bAddr[4][2];
    #pragma unroll
    for (int m = 0; m < 2; m++)
        #pragma unroll
        for (int kk = 0; kk < 2; kk++)
            aAddr[m][kk] = swz((uint32_t)((warp_m * 32 + m * 16 + lr) * 64
                                          + lc * 16 + kk * 32));
    #pragma unroll
    for (int q = 0; q < 4; q++)
        #pragma unroll
        for (int kk = 0; kk < 2; kk++)
            bAddr[q][kk] = swz((uint32_t)((warp_n * 64 + q * 16 + lr) * 64
                                          + lc * 16 + kk * 32));

    for (int c = 0; c < NKI; ++c) {
        cp_wait<GSTAGES - 2>();          // stage c resident
        __syncthreads();                 // all warps done with stage c-1

        if (c + GSTAGES - 1 < NKI)
            gemm_load(sbase, (c + GSTAGES - 1) % GSTAGES, c + GSTAGES - 1,
                      A, B, row0, col0, tid);
        cp_commit();                     // uniform one group per iter

        const uint32_t bb = sbase + (uint32_t)((c % GSTAGES) * 2 * GTILE_B);

        #pragma unroll
        for (int kk = 0; kk < 2; ++kk) {
            uint32_t a[2][4], b[8][2];

            #pragma unroll
            for (int q = 0; q < 4; q++) {
                uint32_t t4[4];
                ldsm4(t4, bb + 1 * GTILE_B + bAddr[q][kk]);
                b[2*q][0] = t4[0]; b[2*q+1][0] = t4[1];
                b[2*q][1] = t4[2]; b[2*q+1][1] = t4[3];
            }
            ldsm4(a[0], bb + aAddr[0][kk]);
            ldsm4(a[1], bb + aAddr[1][kk]);
            #pragma unroll
            for (int m = 0; m < 2; m++)
                #pragma unroll
                for (int n = 0; n < 8; n++) mma16816(acc[m][n], a[m], b[n]);
        }
    }

    // Epilogue
    const int tr = lane >> 2;
    const int tc = (lane & 3) * 2;
    #pragma unroll
    for (int m = 0; m < 2; m++) {
        const int rbase = row0 + warp_m * 32 + m * 16 + tr;
        #pragma unroll
        for (int n = 0; n < 8; n++) {
            const int col = col0 + warp_n * 64 + n * 8 + tc;
            float* p0 = C + (size_t)rbase * DIM + col;
            float* p1 = C + (size_t)(rbase + 8) * DIM + col;
            *(float2*)p0 = make_float2(acc[m][n][0], acc[m][n][1]);
            *(float2*)p1 = make_float2(acc[m][n][2], acc[m][n][3]);
        }
    }
}

__global__ __launch_bounds__(256, 2) void gemm1_kernel() {
    gemm_body(g_xh, g_wi, g_i);
}
__global__ __launch_bounds__(256, 2) void gemm2_kernel(float* __restrict__ out) {
    gemm_body(g_yh, g_wo, out);
}

// ---------------------------------------------------------------------------
// es via HMMA: [e|s][Mx16] = xh * Wes^T
// ---------------------------------------------------------------------------
#define ETILE_B 4096             // 128 rows x 32B
#define ES_PITCH 520
#define ESTAGES 3
#define ENKI 32

struct __align__(128) EsSmem {
    char abuf[ESTAGES][ETILE_B];     // 12 KB
    __half w[16 * ES_PITCH];         // 16640 B
};

__device__ __forceinline__ void es_load(uint32_t sbase, int stage, int c,
                                        int row0, int r) {
    #pragma unroll
    for (int h = 0; h < 2; ++h) {
        cp16(sbase + (uint32_t)(stage * ETILE_B)
                   + swz((uint32_t)(r * 32 + h * 16)),
             g_xh + (size_t)(row0 + r) * DIM + c * 16 + h * 8);
    }
}

__global__ __launch_bounds__(128, 4) void es_mma_kernel() {
    __shared__ EsSmem sm;
    const uint32_t sbase = smem_to_u32(&sm);
    const uint32_t wbase = smem_to_u32(sm.w);
    const int tid = threadIdx.x;
    const int lane = tid & 31;
    const int wid = tid >> 5;            // 0..3
    const int row0 = blockIdx.x * 128;
    const int r = tid;

    {
        const int row = tid >> 3;              // 0..15
        const int colb = (tid & 7) * 64;       // 0..448
        #pragma unroll
        for (int q = 0; q < 8; ++q) {
            uint4 v = *(const uint4*)(g_wes + row * DIM + colb + q * 8);
            *(uint4*)(sm.w + row * ES_PITCH + colb + q * 8) = v;
        }
    }

    #pragma unroll
    for (int s = 0; s < ESTAGES - 1; ++s) {
        es_load(sbase, s, s, row0, r);
        cp_commit();
    }

    const int lr = lane & 15;
    const int lc = (lane >> 4) & 1;
    uint32_t aAddr[2];
    #pragma unroll
    for (int m = 0; m < 2; m++)
        aAddr[m] = swz((uint32_t)((wid * 32 + m * 16 + lr) * 32 + lc * 16));

    float acc[2][2][4];
    #pragma unroll
    for (int m = 0; m < 2; m++)
        #pragma unroll
        for (int n = 0; n < 2; n++)
            #pragma unroll
            for (int q = 0; q < 4; q++) acc[m][n][q] = 0.0f;

    for (int c = 0; c < ENKI; ++c) {
        cp_wait<ESTAGES - 2>();
        __syncthreads();

        if (c + ESTAGES - 1 < ENKI) {
            int st = (c + ESTAGES - 1) % ESTAGES;
            es_load(sbase, st, c + ESTAGES - 1, row0, r);
        }
        cp_commit();

        uint32_t b[2][2];
        #pragma unroll
        for (int nt = 0; nt < 2; ++nt) {
            const uint32_t base = wbase
                + (uint32_t)(((nt * 8 + (lane >> 2)) * ES_PITCH + c * 16 + (lane & 3) * 2) * 2);
            asm volatile("ld.shared.b32 %0, [%1];" : "=r"(b[nt][0]) : "r"(base));
            asm volatile("ld.shared.b32 %0, [%1];" : "=r"(b[nt][1]) : "r"(base + 16));
        }

        const uint32_t ab = sbase + (uint32_t)((c % ESTAGES) * ETILE_B);
        uint32_t a[4];
        #pragma unroll
        for (int m = 0; m < 2; m++) {
            ldsm4(a, ab + aAddr[m]);
            mma16816(acc[m][0], a, b[0]);
            mma16816(acc[m][1], a, b[1]);
        }
    }

    const int tr = lane >> 2;
    const int tc = (lane & 3) * 2;
    #pragma unroll
    for (int m = 0; m < 2; m++) {
        const int rbase = row0 + wid * 32 + m * 16 + tr;
        #pragma unroll
        for (int nt = 0; nt < 2; nt++) {
            float* dst = nt ? g_s : g_e;
            *(float2*)(dst + (size_t)rbase * KEXP + tc) =
                make_float2(acc[m][nt][0], acc[m][nt][1]);
            *(float2*)(dst + (size_t)(rbase + 8) * KEXP + tc) =
                make_float2(acc[m][nt][2], acc[m][nt][3]);
        }
    }
}

// ---------------------------------------------------------------------------
// Fused conversions: one launch.
// ---------------------------------------------------------------------------
#define CVT_XBLOCKS (ROWS * DIM / 4 / 256)   // 8192

__global__ __launch_bounds__(256) void convert_all_kernel(
        const float* __restrict__ x,
        const float* __restrict__ W_i, const float* __restrict__ W_out,
        const float* __restrict__ W_e, const float* __restrict__ W_s) {
    __shared__ float t[32][33];
    const int bid = blockIdx.x;
    const int tid = threadIdx.x;

    if (bid < CVT_XBLOCKS) {
        const size_t i = (size_t)bid * 256 + tid;   // float4 index
        float4 v = ((const float4*)x)[i];
        __half h[4];
        h[0] = __float2half(v.x);
        h[1] = __float2half(v.y);
        h[2] = __float2half(v.z);
        h[3] = __float2half(v.w);
        ((uint2*)g_xh)[i] = *(uint2*)h;
    } else if (bid < CVT_XBLOCKS + 512) {
        const int idx = bid - CVT_XBLOCKS;          // 0..511
        const int z = idx >> 8;                      // 0..1
        const float* W = z ? W_out : W_i;
        __half* D = z ? g_wo : g_wi;
        const int n0 = (idx & 15) * 32;
        const int k0 = ((idx >> 4) & 15) * 32;
        const int tx = tid & 31, ty = tid >> 5;      // 32 x 8
        #pragma unroll
        for (int j = 0; j < 4; ++j)
            t[ty + j * 8][tx] = W[(size_t)(k0 + ty + j * 8) * DIM + n0 + tx];
        __syncthreads();
        #pragma unroll
        for (int j = 0; j < 4; ++j) {
            const int nn = ty + j * 8;
            D[(size_t)(n0 + nn) * DIM + k0 + tx] = __float2half(t[tx][nn]);
        }
    } else {
        for (int e = tid; e < 16 * DIM; e += 256) {
            const int j = e >> 9, d = e & 511;
            const float v = (j < 8) ? W_e[d * KEXP + j] : W_s[d * KEXP + j - 8];
            g_wes[e] = __float2half(v);
        }
    }
}

// ---------------------------------------------------------------------------
// Decay helper
// ---------------------------------------------------------------------------
__device__ __forceinline__ void load_decay(const float* __restrict__ o_param,
                                           int d, float scale, float o[KEXP]) {
    #pragma unroll
    for (int k = 0; k < KEXP; k++) {
        float op = o_param[k * DIM + d];
        float ls = fminf(op, 0.0f) - log1pf(expf(-fabsf(op)));
        o[k] = expf(ls * scale);
    }
}

// ---------------------------------------------------------------------------
// Scan phase 1: per-chunk local end state. iv loads prefetched in batches of
// 8 (MLP=8); recurrence chain unchanged (bit-identical numerics).
// ---------------------------------------------------------------------------
__global__ __launch_bounds__(DIM) void scan_local_kernel(const float* __restrict__ o_param) {
    const int c = blockIdx.x, b = blockIdx.y, d = threadIdx.x;
    float o[KEXP], m[KEXP];
    load_decay(o_param, d, INV_TAU, o);
    #pragma unroll
    for (int k = 0; k < KEXP; k++) m[k] = 0.0f;

    const int t0 = c * CHUNK;
    const float* ip = g_i + ((size_t)b * SEQ + t0) * DIM + d;
    const float* ep = g_e + ((size_t)b * SEQ + t0) * KEXP;

    for (int tb = 0; tb < CHUNK; tb += 8) {
        float iv[8];
        #pragma unroll
        for (int j = 0; j < 8; ++j)
            iv[j] = ip[(size_t)(tb + j) * DIM];

        #pragma unroll
        for (int j = 0; j < 8; ++j) {
            const int t = tb + j;
            float4 e0 = *(const float4*)(ep + t * KEXP);
            float4 e1 = *(const float4*)(ep + t * KEXP + 4);
            float ev[KEXP] = {e0.x, e0.y, e0.z, e0.w, e1.x, e1.y, e1.z, e1.w};
            #pragma unroll
            for (int k = 0; k < KEXP; k++)
                m[k] = fmaf(o[k], m[k], ev[k] * iv[j]);
        }
    }
    #pragma unroll
    for (int k = 0; k < KEXP; k++)
        g_S[(((size_t)b * NCHUNK + c) * KEXP + k) * DIM + d] = m[k];
}

// ---------------------------------------------------------------------------
// Scan phase 2: prefix over chunks; loads hoisted for MLP.
// ---------------------------------------------------------------------------
__global__ __launch_bounds__(DIM) void scan_prefix_kernel(const float* __restrict__ o_param) {
    const int b = blockIdx.x;
    const int kp = blockIdx.y * 2;
    const int d = threadIdx.x;

    float oL0, oL1;
    {
        float op0 = o_param[kp * DIM + d];
        float op1 = o_param[(kp + 1) * DIM + d];
        float ls0 = fminf(op0, 0.0f) - log1pf(expf(-fabsf(op0)));
        float ls1 = fminf(op1, 0.0f) - log1pf(expf(-fabsf(op1)));
        oL0 = expf(ls0 * (INV_TAU * (float)CHUNK));
        oL1 = expf(ls1 * (INV_TAU * (float)CHUNK));
    }

    float s0[NCHUNK], s1[NCHUNK];
    #pragma unroll
    for (int c = 0; c < NCHUNK; c++) {
        s0[c] = g_S[(((size_t)b * NCHUNK + c) * KEXP + kp) * DIM + d];
        s1[c] = g_S[(((size_t)b * NCHUNK + c) * KEXP + kp + 1) * DIM + d];
    }
    float p0 = 0.0f, p1 = 0.0f;
    #pragma unroll
    for (int c = 0; c < NCHUNK; c++) {
        g_P[(((size_t)b * NCHUNK + c) * KEXP + kp) * DIM + d] = p0;
        g_P[(((size_t)b * NCHUNK + c) * KEXP + kp + 1) * DIM + d] = p1;
        p0 = fmaf(oL0, p0, s0[c]);
        p1 = fmaf(oL1, p1, s1[c]);
    }
}

// ---------------------------------------------------------------------------
// Scan phase 3 + LayerNorm fused. iv loads for the whole 16-step group are
// prefetched into registers (MLP=16) before the serial chain.
// grid (NCHUNK, BATCH), block 512, 16 warps.
// ---------------------------------------------------------------------------
#define TG 16   // timesteps buffered per group

__global__ __launch_bounds__(DIM) void scan_apply_ln_kernel(const float* __restrict__ o_param,
                                                            const float* __restrict__ gamma,
                                                            const float* __restrict__ beta) {
    __shared__ float ybuf[TG][DIM];
    __shared__ float smu[TG], srstd[TG];

    const int c = blockIdx.x, b = blockIdx.y, d = threadIdx.x;
    const int lane = d & 31, warp = d >> 5;

    float o[KEXP], m[KEXP];
    load_decay(o_param, d, INV_TAU, o);
    #pragma unroll
    for (int k = 0; k < KEXP; k++)
        m[k] = g_P[(((size_t)b * NCHUNK + c) * KEXP + k) * DIM + d];

    const float gam = gamma[d];
    const float bet = beta[d];

    const int t0 = c * CHUNK;
    const size_t rowbase = (size_t)b * SEQ + t0;
    const float* ip = g_i + rowbase * DIM + d;
    const float* ep = g_e + rowbase * KEXP;
    const float* sp = g_s + rowbase * KEXP;

    for (int g = 0; g < CHUNK / TG; ++g) {
        // Prefetch all 16 strided iv loads (independent; MLP=16)
        float iv[TG];
        #pragma unroll
        for (int tt = 0; tt < TG; ++tt)
            iv[tt] = ip[(size_t)(g * TG + tt) * DIM];

        #pragma unroll 4
        for (int tt = 0; tt < TG; ++tt) {
            const int t = g * TG + tt;
            float4 e0 = *(const float4*)(ep + t * KEXP);
            float4 e1 = *(const float4*)(ep + t * KEXP + 4);
            float4 s0 = *(const float4*)(sp + t * KEXP);
            float4 s1 = *(const float4*)(sp + t * KEXP + 4);
            float ev[KEXP] = {e0.x, e0.y, e0.z, e0.w, e1.x, e1.y, e1.z, e1.w};
            float sv[KEXP] = {s0.x, s0.y, s0.z, s0.w, s1.x, s1.y, s1.z, s1.w};
            float y0 = 0.0f, y1 = 0.0f;
            #pragma unroll
            for (int k = 0; k < KEXP; k += 2) {
                m[k]     = fmaf(o[k],     m[k],     ev[k]     * iv[tt]);
                m[k + 1] = fmaf(o[k + 1], m[k + 1], ev[k + 1] * iv[tt]);
                y0 = fmaf(sv[k],     m[k],     y0);
                y1 = fmaf(sv[k + 1], m[k + 1], y1);
            }
            ybuf[tt][d] = y0 + y1;
        }
        __syncthreads();

        // warp w reduces timestep tt=w over the full 512-dim row
        {
            float s1r = 0.0f, s2r = 0.0f;
            #pragma unroll
            for (int j = 0; j < 16; ++j) {
                const float v = ybuf[warp][lane + j * 32];
                s1r += v;
                s2r = fmaf(v, v, s2r);
            }
            #pragma unroll
            for (int off = 16; off > 0; off >>= 1) {
                s1r += __shfl_xor_sync(0xFFFFFFFFu, s1r, off);
                s2r += __shfl_xor_sync(0xFFFFFFFFu, s2r, off);
            }
            if (lane == 0) {
                const float mu = s1r * (1.0f / DIM);
                const float var = s2r * (1.0f / DIM) - mu * mu;
                smu[warp] = mu;
                srstd[warp] = rsqrtf(var + LN_EPS);
            }
        }
        __syncthreads();

        #pragma unroll 4
        for (int tt = 0; tt < TG; ++tt) {
            const size_t row = rowbase + g * TG + tt;
            const float rv = fmaf((ybuf[tt][d] - smu[tt]) * srstd[tt], gam, bet);
            g_yh[row * DIM + d] = __float2half(rv);
        }
        __syncthreads();
    }
}

// ---------------------------------------------------------------------------
// Launch
// ---------------------------------------------------------------------------
extern "C" void kernel_launch(void* const* d_in, const int* in_sizes, int n_in,
                              void* d_out, int out_size) {
    const float* x       = (const float*)d_in[0];
    const float* W_i     = (const float*)d_in[1];
    const float* W_e     = (const float*)d_in[2];
    const float* W_s     = (const float*)d_in[3];
    const float* o_param = (const float*)d_in[4];
    const float* gamma   = (const float*)d_in[5];
    const float* beta    = (const float*)d_in[6];
    const float* W_out   = (const float*)d_in[7];
    float* out = (float*)d_out;

    convert_all_kernel<<<CVT_XBLOCKS + 512 + 1, 256>>>(x, W_i, W_out, W_e, W_s);
    gemm1_kernel<<<dim3(4, 128), 256>>>();
    es_mma_kernel<<<128, 128>>>();
    scan_local_kernel<<<dim3(NCHUNK, BATCH), DIM>>>(o_param);
    scan_prefix_kernel<<<dim3(BATCH, KEXP / 2), DIM>>>(o_param);
    scan_apply_ln_kernel<<<dim3(NCHUNK, BATCH), DIM>>>(o_param, gamma, beta);
    gemm2_kernel<<<dim3(4, 128), 256>>>(out);
}

// round 12
// speedup vs baseline: 1.6695x; 1.0186x over previous
#include <cuda_runtime.h>
#include <cuda_fp16.h>
#include <math.h>
#include <cstdint>

// Problem constants
#define BATCH 4
#define SEQ   4096
#define DIM   512
#define KEXP  8
#define ROWS  (BATCH*SEQ)        // 16384 token rows
#define CHUNK 128                // scan chunk length
#define NCHUNK (SEQ/CHUNK)       // 32 chunks
#define INV_TAU (1.0f/16.0f)
#define LN_EPS 1e-5f

// ---------------------------------------------------------------------------
// Scratch (static device globals)
// ---------------------------------------------------------------------------
__device__ float g_i[ROWS * DIM];                       // x @ W_i (fp32)
__device__ float g_e[ROWS * KEXP];
__device__ float g_s[ROWS * KEXP];
__device__ float g_S[BATCH * NCHUNK * KEXP * DIM];
__device__ float g_P[BATCH * NCHUNK * KEXP * DIM];
__device__ __half g_xh[ROWS * DIM];                     // fp16(x)
__device__ __half g_yh[ROWS * DIM];                     // fp16(LN(y))
__device__ __half g_wi[DIM * DIM];                      // W_i^T  [N,K] fp16
__device__ __half g_wo[DIM * DIM];                      // W_out^T [N,K] fp16
__device__ __half g_wes[16 * DIM];                      // [W_e|W_s]^T [16,K] fp16

// ---------------------------------------------------------------------------
// PTX primitives (baseline sm_80+ — legal for compute_103 PTX target)
// ---------------------------------------------------------------------------
__device__ __forceinline__ uint32_t smem_to_u32(const void* p) {
    uint32_t a;
    asm("{ .reg .u64 t; cvta.to.shared.u64 t, %1; cvt.u32.u64 %0, t; }" : "=r"(a) : "l"(p));
    return a;
}

__device__ __forceinline__ void cp16(uint32_t dst, const void* src) {
    asm volatile("cp.async.cg.shared.global [%0], [%1], 16;" :: "r"(dst), "l"(src));
}
__device__ __forceinline__ void cp_commit() {
    asm volatile("cp.async.commit_group;" ::: "memory");
}
template <int N>
__device__ __forceinline__ void cp_wait() {
    asm volatile("cp.async.wait_group %0;" :: "n"(N) : "memory");
}

__device__ __forceinline__ void ldsm4(uint32_t* r, uint32_t addr) {
    asm volatile("ldmatrix.sync.aligned.m8n8.x4.shared.b16 {%0,%1,%2,%3}, [%4];"
                 : "=r"(r[0]), "=r"(r[1]), "=r"(r[2]), "=r"(r[3]) : "r"(addr));
}

__device__ __forceinline__ void mma16816(float* c, const uint32_t* a, const uint32_t* b) {
    asm volatile(
        "mma.sync.aligned.m16n8k16.row.col.f32.f16.f16.f32 "
        "{%0,%1,%2,%3}, {%4,%5,%6,%7}, {%8,%9}, {%0,%1,%2,%3};"
        : "+f"(c[0]), "+f"(c[1]), "+f"(c[2]), "+f"(c[3])
        : "r"(a[0]), "r"(a[1]), "r"(a[2]), "r"(a[3]), "r"(b[0]), "r"(b[1]));
}

// Swizzle: XOR bits[4:5] with bits[7:8], applied to the FINAL 16B-chunk offset.
__device__ __forceinline__ uint32_t swz(uint32_t off) {
    return off ^ (((off >> 7) & 3u) << 4);
}

// ---------------------------------------------------------------------------
// HMMA fp16 GEMM: C[Mx512] = A * B^T (single-term fp16). Unchanged from R11.
// ---------------------------------------------------------------------------
#define BK 32
#define NKI (DIM/BK)             // 16 k-iterations
#define GTILE_B 8192             // bytes per tile (128 rows x 64B)
#define GSTAGES 3

struct __align__(128) GemmSmem { char buf[GSTAGES][2][GTILE_B]; };  // 48 KB

__device__ __forceinline__ void gemm_load(uint32_t sbase, int stage, int c,
                                          const __half* A, const __half* B,
                                          int row0, int col0, int tid) {
    const int r = tid >> 1;              // 0..127
    const int h = tid & 1;               // 32B half of the 64B row
    const uint32_t so0 = swz((uint32_t)(r * 64 + h * 32));
    const uint32_t so1 = swz((uint32_t)(r * 64 + h * 32 + 16));
    const size_t ga = (size_t)(row0 + r) * DIM + c * BK + h * 16;
    const size_t gb = (size_t)(col0 + r) * DIM + c * BK + h * 16;
    const uint32_t base = sbase + (uint32_t)(stage * 2 * GTILE_B);
    cp16(base + 0 * GTILE_B + so0, A + ga);
    cp16(base + 0 * GTILE_B + so1, A + ga + 8);
    cp16(base + 1 * GTILE_B + so0, B + gb);
    cp16(base + 1 * GTILE_B + so1, B + gb + 8);
}

__device__ __forceinline__ void gemm_body(const __half* __restrict__ A,
                                          const __half* __restrict__ B,
                                          float* __restrict__ C) {
    __shared__ GemmSmem sm;
    const uint32_t sbase = smem_to_u32(&sm);
    const int tid = threadIdx.x;
    const int lane = tid & 31;
    const int wid = tid >> 5;
    const int warp_m = wid >> 1;
    const int warp_n = wid & 1;
    const int row0 = blockIdx.y * 128;
    const int col0 = blockIdx.x * 128;

    const int lr = lane & 15;
    const int lc = (lane >> 4) & 1;

    float acc[2][8][4];
    #pragma unroll
    for (int m = 0; m < 2; m++)
        #pragma unroll
        for (int n = 0; n < 8; n++)
            #pragma unroll
            for (int q = 0; q < 4; q++) acc[m][n][q] = 0.0f;

    #pragma unroll
    for (int s = 0; s < GSTAGES - 1; ++s) {
        gemm_load(sbase, s, s, A, B, row0, col0, tid);
        cp_commit();
    }

    uint32_t aAddr[2][2], bAddr[4][2];
    #pragma unroll
    for (int m = 0; m < 2; m++)
        #pragma unroll
        for (int kk = 0; kk < 2; kk++)
            aAddr[m][kk] = swz((uint32_t)((warp_m * 32 + m * 16 + lr) * 64
                                          + lc * 16 + kk * 32));
    #pragma unroll
    for (int q = 0; q < 4; q++)
        #pragma unroll
        for (int kk = 0; kk < 2; kk++)
            bAddr[q][kk] = swz((uint32_t)((warp_n * 64 + q * 16 + lr) * 64
                                          + lc * 16 + kk * 32));

    for (int c = 0; c < NKI; ++c) {
        cp_wait<GSTAGES - 2>();
        __syncthreads();

        if (c + GSTAGES - 1 < NKI)
            gemm_load(sbase, (c + GSTAGES - 1) % GSTAGES, c + GSTAGES - 1,
                      A, B, row0, col0, tid);
        cp_commit();

        const uint32_t bb = sbase + (uint32_t)((c % GSTAGES) * 2 * GTILE_B);

        #pragma unroll
        for (int kk = 0; kk < 2; ++kk) {
            uint32_t a[2][4], b[8][2];
            #pragma unroll
            for (int q = 0; q < 4; q++) {
                uint32_t t4[4];
                ldsm4(t4, bb + 1 * GTILE_B + bAddr[q][kk]);
                b[2*q][0] = t4[0]; b[2*q+1][0] = t4[1];
                b[2*q][1] = t4[2]; b[2*q+1][1] = t4[3];
            }
            ldsm4(a[0], bb + aAddr[0][kk]);
            ldsm4(a[1], bb + aAddr[1][kk]);
            #pragma unroll
            for (int m = 0; m < 2; m++)
                #pragma unroll
                for (int n = 0; n < 8; n++) mma16816(acc[m][n], a[m], b[n]);
        }
    }

    const int tr = lane >> 2;
    const int tc = (lane & 3) * 2;
    #pragma unroll
    for (int m = 0; m < 2; m++) {
        const int rbase = row0 + warp_m * 32 + m * 16 + tr;
        #pragma unroll
        for (int n = 0; n < 8; n++) {
            const int col = col0 + warp_n * 64 + n * 8 + tc;
            float* p0 = C + (size_t)rbase * DIM + col;
            float* p1 = C + (size_t)(rbase + 8) * DIM + col;
            *(float2*)p0 = make_float2(acc[m][n][0], acc[m][n][1]);
            *(float2*)p1 = make_float2(acc[m][n][2], acc[m][n][3]);
        }
    }
}

__global__ __launch_bounds__(256, 2) void gemm1_kernel() {
    gemm_body(g_xh, g_wi, g_i);
}
__global__ __launch_bounds__(256, 2) void gemm2_kernel(float* __restrict__ out) {
    gemm_body(g_yh, g_wo, out);
}

// ---------------------------------------------------------------------------
// es via HMMA (unchanged from R11)
// ---------------------------------------------------------------------------
#define ETILE_B 4096
#define ES_PITCH 520
#define ESTAGES 3
#define ENKI 32

struct __align__(128) EsSmem {
    char abuf[ESTAGES][ETILE_B];
    __half w[16 * ES_PITCH];
};

__device__ __forceinline__ void es_load(uint32_t sbase, int stage, int c,
                                        int row0, int r) {
    #pragma unroll
    for (int h = 0; h < 2; ++h) {
        cp16(sbase + (uint32_t)(stage * ETILE_B)
                   + swz((uint32_t)(r * 32 + h * 16)),
             g_xh + (size_t)(row0 + r) * DIM + c * 16 + h * 8);
    }
}

__global__ __launch_bounds__(128, 4) void es_mma_kernel() {
    __shared__ EsSmem sm;
    const uint32_t sbase = smem_to_u32(&sm);
    const uint32_t wbase = smem_to_u32(sm.w);
    const int tid = threadIdx.x;
    const int lane = tid & 31;
    const int wid = tid >> 5;
    const int row0 = blockIdx.x * 128;
    const int r = tid;

    {
        const int row = tid >> 3;
        const int colb = (tid & 7) * 64;
        #pragma unroll
        for (int q = 0; q < 8; ++q) {
            uint4 v = *(const uint4*)(g_wes + row * DIM + colb + q * 8);
            *(uint4*)(sm.w + row * ES_PITCH + colb + q * 8) = v;
        }
    }

    #pragma unroll
    for (int s = 0; s < ESTAGES - 1; ++s) {
        es_load(sbase, s, s, row0, r);
        cp_commit();
    }

    const int lr = lane & 15;
    const int lc = (lane >> 4) & 1;
    uint32_t aAddr[2];
    #pragma unroll
    for (int m = 0; m < 2; m++)
        aAddr[m] = swz((uint32_t)((wid * 32 + m * 16 + lr) * 32 + lc * 16));

    float acc[2][2][4];
    #pragma unroll
    for (int m = 0; m < 2; m++)
        #pragma unroll
        for (int n = 0; n < 2; n++)
            #pragma unroll
            for (int q = 0; q < 4; q++) acc[m][n][q] = 0.0f;

    for (int c = 0; c < ENKI; ++c) {
        cp_wait<ESTAGES - 2>();
        __syncthreads();

        if (c + ESTAGES - 1 < ENKI) {
            int st = (c + ESTAGES - 1) % ESTAGES;
            es_load(sbase, st, c + ESTAGES - 1, row0, r);
        }
        cp_commit();

        uint32_t b[2][2];
        #pragma unroll
        for (int nt = 0; nt < 2; ++nt) {
            const uint32_t base = wbase
                + (uint32_t)(((nt * 8 + (lane >> 2)) * ES_PITCH + c * 16 + (lane & 3) * 2) * 2);
            asm volatile("ld.shared.b32 %0, [%1];" : "=r"(b[nt][0]) : "r"(base));
            asm volatile("ld.shared.b32 %0, [%1];" : "=r"(b[nt][1]) : "r"(base + 16));
        }

        const uint32_t ab = sbase + (uint32_t)((c % ESTAGES) * ETILE_B);
        uint32_t a[4];
        #pragma unroll
        for (int m = 0; m < 2; m++) {
            ldsm4(a, ab + aAddr[m]);
            mma16816(acc[m][0], a, b[0]);
            mma16816(acc[m][1], a, b[1]);
        }
    }

    const int tr = lane >> 2;
    const int tc = (lane & 3) * 2;
    #pragma unroll
    for (int m = 0; m < 2; m++) {
        const int rbase = row0 + wid * 32 + m * 16 + tr;
        #pragma unroll
        for (int nt = 0; nt < 2; nt++) {
            float* dst = nt ? g_s : g_e;
            *(float2*)(dst + (size_t)rbase * KEXP + tc) =
                make_float2(acc[m][nt][0], acc[m][nt][1]);
            *(float2*)(dst + (size_t)(rbase + 8) * KEXP + tc) =
                make_float2(acc[m][nt][2], acc[m][nt][3]);
        }
    }
}

// ---------------------------------------------------------------------------
// Fused conversions: one launch (unchanged)
// ---------------------------------------------------------------------------
#define CVT_XBLOCKS (ROWS * DIM / 4 / 256)   // 8192

__global__ __launch_bounds__(256) void convert_all_kernel(
        const float* __restrict__ x,
        const float* __restrict__ W_i, const float* __restrict__ W_out,
        const float* __restrict__ W_e, const float* __restrict__ W_s) {
    __shared__ float t[32][33];
    const int bid = blockIdx.x;
    const int tid = threadIdx.x;

    if (bid < CVT_XBLOCKS) {
        const size_t i = (size_t)bid * 256 + tid;
        float4 v = ((const float4*)x)[i];
        __half h[4];
        h[0] = __float2half(v.x);
        h[1] = __float2half(v.y);
        h[2] = __float2half(v.z);
        h[3] = __float2half(v.w);
        ((uint2*)g_xh)[i] = *(uint2*)h;
    } else if (bid < CVT_XBLOCKS + 512) {
        const int idx = bid - CVT_XBLOCKS;
        const int z = idx >> 8;
        const float* W = z ? W_out : W_i;
        __half* D = z ? g_wo : g_wi;
        const int n0 = (idx & 15) * 32;
        const int k0 = ((idx >> 4) & 15) * 32;
        const int tx = tid & 31, ty = tid >> 5;
        #pragma unroll
        for (int j = 0; j < 4; ++j)
            t[ty + j * 8][tx] = W[(size_t)(k0 + ty + j * 8) * DIM + n0 + tx];
        __syncthreads();
        #pragma unroll
        for (int j = 0; j < 4; ++j) {
            const int nn = ty + j * 8;
            D[(size_t)(n0 + nn) * DIM + k0 + tx] = __float2half(t[tx][nn]);
        }
    } else {
        for (int e = tid; e < 16 * DIM; e += 256) {
            const int j = e >> 9, d = e & 511;
            const float v = (j < 8) ? W_e[d * KEXP + j] : W_s[d * KEXP + j - 8];
            g_wes[e] = __float2half(v);
        }
    }
}

// ---------------------------------------------------------------------------
// Decay helper
// ---------------------------------------------------------------------------
__device__ __forceinline__ void load_decay(const float* __restrict__ o_param,
                                           int d, float scale, float o[KEXP]) {
    #pragma unroll
    for (int k = 0; k < KEXP; k++) {
        float op = o_param[k * DIM + d];
        float ls = fminf(op, 0.0f) - log1pf(expf(-fabsf(op)));
        o[k] = expf(ls * scale);
    }
}

// ---------------------------------------------------------------------------
// Scan phase 1: per-chunk local end state. iv tiles staged through SMEM with
// a 3-stage cp.async ring (8 timesteps x 2KB per stage; 48KB static).
// FMA order unchanged -> bit-identical numerics.
// ---------------------------------------------------------------------------
#define SL_TG 8
#define SL_STAGES 3
#define SL_NS (CHUNK/SL_TG)     // 16 stages of work

__global__ __launch_bounds__(DIM) void scan_local_kernel(const float* __restrict__ o_param) {
    __shared__ float ivb[SL_STAGES][SL_TG][DIM];   // 49152 B
    const uint32_t sb = smem_to_u32(ivb);
    const int c = blockIdx.x, b = blockIdx.y, d = threadIdx.x;
    float o[KEXP], m[KEXP];
    load_decay(o_param, d, INV_TAU, o);
    #pragma unroll
    for (int k = 0; k < KEXP; k++) m[k] = 0.0f;

    const int t0 = c * CHUNK;
    const float* ibase = g_i + ((size_t)b * SEQ + t0) * DIM;
    const float* ep = g_e + ((size_t)b * SEQ + t0) * KEXP;

    // Prologue: stages 0..1
    #pragma unroll
    for (int s = 0; s < SL_STAGES - 1; ++s) {
        #pragma unroll
        for (int i = 0; i < 2; ++i) {
            const int q = d + i * DIM;                  // 0..1023
            const int tl = q >> 7, col = (q & 127) * 4; // 8 rows x 128 chunks
            cp16(sb + (uint32_t)(((s * SL_TG + tl) * DIM + col) * 4),
                 ibase + (size_t)(s * SL_TG + tl) * DIM + col);
        }
        cp_commit();
    }

    for (int s = 0; s < SL_NS; ++s) {
        cp_wait<SL_STAGES - 2>();
        __syncthreads();

        if (s + SL_STAGES - 1 < SL_NS) {
            const int ns = s + SL_STAGES - 1;
            const int st = ns % SL_STAGES;
            #pragma unroll
            for (int i = 0; i < 2; ++i) {
                const int q = d + i * DIM;
                const int tl = q >> 7, col = (q & 127) * 4;
                cp16(sb + (uint32_t)(((st * SL_TG + tl) * DIM + col) * 4),
                     ibase + (size_t)(ns * SL_TG + tl) * DIM + col);
            }
        }
        cp_commit();

        const int st = s % SL_STAGES;
        #pragma unroll
        for (int j = 0; j < SL_TG; ++j) {
            const int t = s * SL_TG + j;
            const float iv = ivb[st][j][d];
            float4 e0 = *(const float4*)(ep + t * KEXP);
            float4 e1 = *(const float4*)(ep + t * KEXP + 4);
            float ev[KEXP] = {e0.x, e0.y, e0.z, e0.w, e1.x, e1.y, e1.z, e1.w};
            #pragma unroll
            for (int k = 0; k < KEXP; k++)
                m[k] = fmaf(o[k], m[k], ev[k] * iv);
        }
    }
    #pragma unroll
    for (int k = 0; k < KEXP; k++)
        g_S[(((size_t)b * NCHUNK + c) * KEXP + k) * DIM + d] = m[k];
}

// ---------------------------------------------------------------------------
// Scan phase 2: prefix over chunks (unchanged)
// ---------------------------------------------------------------------------
__global__ __launch_bounds__(DIM) void scan_prefix_kernel(const float* __restrict__ o_param) {
    const int b = blockIdx.x;
    const int kp = blockIdx.y * 2;
    const int d = threadIdx.x;

    float oL0, oL1;
    {
        float op0 = o_param[kp * DIM + d];
        float op1 = o_param[(kp + 1) * DIM + d];
        float ls0 = fminf(op0, 0.0f) - log1pf(expf(-fabsf(op0)));
        float ls1 = fminf(op1, 0.0f) - log1pf(expf(-fabsf(op1)));
        oL0 = expf(ls0 * (INV_TAU * (float)CHUNK));
        oL1 = expf(ls1 * (INV_TAU * (float)CHUNK));
    }

    float s0[NCHUNK], s1[NCHUNK];
    #pragma unroll
    for (int c = 0; c < NCHUNK; c++) {
        s0[c] = g_S[(((size_t)b * NCHUNK + c) * KEXP + kp) * DIM + d];
        s1[c] = g_S[(((size_t)b * NCHUNK + c) * KEXP + kp + 1) * DIM + d];
    }
    float p0 = 0.0f, p1 = 0.0f;
    #pragma unroll
    for (int c = 0; c < NCHUNK; c++) {
        g_P[(((size_t)b * NCHUNK + c) * KEXP + kp) * DIM + d] = p0;
        g_P[(((size_t)b * NCHUNK + c) * KEXP + kp + 1) * DIM + d] = p1;
        p0 = fmaf(oL0, p0, s0[c]);
        p1 = fmaf(oL1, p1, s1[c]);
    }
}

// ---------------------------------------------------------------------------
// Scan phase 3 + LayerNorm. iv tiles staged via 2-stage cp.async ring
// (16 timesteps x 32KB per stage) in dynamic SMEM alongside ybuf:
//   [0, 32KB)  ybuf[16][512]
//   [32KB,96KB) ivb[2][16][512]
// grid (NCHUNK, BATCH), block 512, 16 warps.
// ---------------------------------------------------------------------------
#define TG 16
#define AP_GROUPS (CHUNK/TG)          // 8
#define AP_DYN ((TG + 2*TG) * DIM * 4) // 98304

__global__ __launch_bounds__(DIM) void scan_apply_ln_kernel(const float* __restrict__ o_param,
                                                            const float* __restrict__ gamma,
                                                            const float* __restrict__ beta) {
    extern __shared__ float dyn[];
    float (*ybuf)[DIM] = (float(*)[DIM])dyn;
    float* ivb = dyn + TG * DIM;              // [2][TG][DIM]
    const uint32_t ivb_u = smem_to_u32(ivb);
    __shared__ float smu[TG], srstd[TG];

    const int c = blockIdx.x, b = blockIdx.y, d = threadIdx.x;
    const int lane = d & 31, warp = d >> 5;

    float o[KEXP], m[KEXP];
    load_decay(o_param, d, INV_TAU, o);
    #pragma unroll
    for (int k = 0; k < KEXP; k++)
        m[k] = g_P[(((size_t)b * NCHUNK + c) * KEXP + k) * DIM + d];

    const float gam = gamma[d];
    const float bet = beta[d];

    const int t0 = c * CHUNK;
    const size_t rowbase = (size_t)b * SEQ + t0;
    const float* ibase = g_i + rowbase * DIM;
    const float* ep = g_e + rowbase * KEXP;
    const float* sp = g_s + rowbase * KEXP;

    // Prologue: load group 0 into stage 0 (4 cp16 per thread)
    #pragma unroll
    for (int i = 0; i < 4; ++i) {
        const int q = d + i * DIM;                  // 0..2047
        const int tl = q >> 7, col = (q & 127) * 4;
        cp16(ivb_u + (uint32_t)((tl * DIM + col) * 4),
             ibase + (size_t)tl * DIM + col);
    }
    cp_commit();

    for (int g = 0; g < AP_GROUPS; ++g) {
        cp_wait<0>();
        __syncthreads();

        if (g + 1 < AP_GROUPS) {
            const int st = (g + 1) & 1;
            #pragma unroll
            for (int i = 0; i < 4; ++i) {
                const int q = d + i * DIM;
                const int tl = q >> 7, col = (q & 127) * 4;
                cp16(ivb_u + (uint32_t)(((st * TG + tl) * DIM + col) * 4),
                     ibase + (size_t)((g + 1) * TG + tl) * DIM + col);
            }
        }
        cp_commit();

        const float* ivst = ivb + (size_t)(g & 1) * TG * DIM;

        #pragma unroll 4
        for (int tt = 0; tt < TG; ++tt) {
            const int t = g * TG + tt;
            const float iv = ivst[tt * DIM + d];
            float4 e0 = *(const float4*)(ep + t * KEXP);
            float4 e1 = *(const float4*)(ep + t * KEXP + 4);
            float4 s0 = *(const float4*)(sp + t * KEXP);
            float4 s1 = *(const float4*)(sp + t * KEXP + 4);
            float ev[KEXP] = {e0.x, e0.y, e0.z, e0.w, e1.x, e1.y, e1.z, e1.w};
            float sv[KEXP] = {s0.x, s0.y, s0.z, s0.w, s1.x, s1.y, s1.z, s1.w};
            float y0 = 0.0f, y1 = 0.0f;
            #pragma unroll
            for (int k = 0; k < KEXP; k += 2) {
                m[k]     = fmaf(o[k],     m[k],     ev[k]     * iv);
                m[k + 1] = fmaf(o[k + 1], m[k + 1], ev[k + 1] * iv);
                y0 = fmaf(sv[k],     m[k],     y0);
                y1 = fmaf(sv[k + 1], m[k + 1], y1);
            }
            ybuf[tt][d] = y0 + y1;
        }
        __syncthreads();

        // warp w reduces timestep tt=w over the full 512-dim row
        {
            float s1r = 0.0f, s2r = 0.0f;
            #pragma unroll
            for (int j = 0; j < 16; ++j) {
                const float v = ybuf[warp][lane + j * 32];
                s1r += v;
                s2r = fmaf(v, v, s2r);
            }
            #pragma unroll
            for (int off = 16; off > 0; off >>= 1) {
                s1r += __shfl_xor_sync(0xFFFFFFFFu, s1r, off);
                s2r += __shfl_xor_sync(0xFFFFFFFFu, s2r, off);
            }
            if (lane == 0) {
                const float mu = s1r * (1.0f / DIM);
                const float var = s2r * (1.0f / DIM) - mu * mu;
                smu[warp] = mu;
                srstd[warp] = rsqrtf(var + LN_EPS);
            }
        }
        __syncthreads();

        #pragma unroll 4
        for (int tt = 0; tt < TG; ++tt) {
            const size_t row = rowbase + g * TG + tt;
            const float rv = fmaf((ybuf[tt][d] - smu[tt]) * srstd[tt], gam, bet);
            g_yh[row * DIM + d] = __float2half(rv);
        }
    }
}

// ---------------------------------------------------------------------------
// Launch
// ---------------------------------------------------------------------------
extern "C" void kernel_launch(void* const* d_in, const int* in_sizes, int n_in,
                              void* d_out, int out_size) {
    const float* x       = (const float*)d_in[0];
    const float* W_i     = (const float*)d_in[1];
    const float* W_e     = (const float*)d_in[2];
    const float* W_s     = (const float*)d_in[3];
    const float* o_param = (const float*)d_in[4];
    const float* gamma   = (const float*)d_in[5];
    const float* beta    = (const float*)d_in[6];
    const float* W_out   = (const float*)d_in[7];
    float* out = (float*)d_out;

    cudaFuncSetAttribute(scan_apply_ln_kernel,
                         cudaFuncAttributeMaxDynamicSharedMemorySize, AP_DYN);

    convert_all_kernel<<<CVT_XBLOCKS + 512 + 1, 256>>>(x, W_i, W_out, W_e, W_s);
    gemm1_kernel<<<dim3(4, 128), 256>>>();
    es_mma_kernel<<<128, 128>>>();
    scan_local_kernel<<<dim3(NCHUNK, BATCH), DIM>>>(o_param);
    scan_prefix_kernel<<<dim3(BATCH, KEXP / 2), DIM>>>(o_param);
    scan_apply_ln_kernel<<<dim3(NCHUNK, BATCH), DIM, AP_DYN>>>(o_param, gamma, beta);
    gemm2_kernel<<<dim3(4, 128), 256>>>(out);
}

// round 13
// speedup vs baseline: 2.0744x; 1.2425x over previous
#include <cuda_runtime.h>
#include <cuda_fp16.h>
#include <math.h>
#include <cstdint>

// Problem constants
#define BATCH 4
#define SEQ   4096
#define DIM   512
#define KEXP  8
#define ROWS  (BATCH*SEQ)        // 16384 token rows
#define CHUNK 128                // scan chunk length
#define NCHUNK (SEQ/CHUNK)       // 32 chunks
#define INV_TAU (1.0f/16.0f)
#define LN_EPS 1e-5f

// ---------------------------------------------------------------------------
// Scratch (static device globals)
// ---------------------------------------------------------------------------
__device__ float g_i[ROWS * DIM];                       // x @ W_i (fp32)
__device__ float g_e[ROWS * KEXP];
__device__ float g_s[ROWS * KEXP];
__device__ float g_S[BATCH * NCHUNK * KEXP * DIM];
__device__ float g_P[BATCH * NCHUNK * KEXP * DIM];
__device__ __half g_xh[ROWS * DIM];                     // fp16(x)
__device__ __half g_yh[ROWS * DIM];                     // fp16(LN(y))
__device__ __half g_wi[DIM * DIM];                      // W_i^T  [N,K] fp16
__device__ __half g_wo[DIM * DIM];                      // W_out^T [N,K] fp16
__device__ __half g_wes[16 * DIM];                      // [W_e|W_s]^T [16,K] fp16

// ---------------------------------------------------------------------------
// PTX primitives (baseline sm_80+ — legal for compute_103 PTX target)
// ---------------------------------------------------------------------------
__device__ __forceinline__ uint32_t smem_to_u32(const void* p) {
    uint32_t a;
    asm("{ .reg .u64 t; cvta.to.shared.u64 t, %1; cvt.u32.u64 %0, t; }" : "=r"(a) : "l"(p));
    return a;
}

__device__ __forceinline__ void cp16(uint32_t dst, const void* src) {
    asm volatile("cp.async.cg.shared.global [%0], [%1], 16;" :: "r"(dst), "l"(src));
}
__device__ __forceinline__ void cp_commit() {
    asm volatile("cp.async.commit_group;" ::: "memory");
}
template <int N>
__device__ __forceinline__ void cp_wait() {
    asm volatile("cp.async.wait_group %0;" :: "n"(N) : "memory");
}

__device__ __forceinline__ void ldsm4(uint32_t* r, uint32_t addr) {
    asm volatile("ldmatrix.sync.aligned.m8n8.x4.shared.b16 {%0,%1,%2,%3}, [%4];"
                 : "=r"(r[0]), "=r"(r[1]), "=r"(r[2]), "=r"(r[3]) : "r"(addr));
}

__device__ __forceinline__ void mma16816(float* c, const uint32_t* a, const uint32_t* b) {
    asm volatile(
        "mma.sync.aligned.m16n8k16.row.col.f32.f16.f16.f32 "
        "{%0,%1,%2,%3}, {%4,%5,%6,%7}, {%8,%9}, {%0,%1,%2,%3};"
        : "+f"(c[0]), "+f"(c[1]), "+f"(c[2]), "+f"(c[3])
        : "r"(a[0]), "r"(a[1]), "r"(a[2]), "r"(a[3]), "r"(b[0]), "r"(b[1]));
}

// Swizzle: XOR bits[4:5] with bits[7:8], applied to the FINAL 16B-chunk offset.
__device__ __forceinline__ uint32_t swz(uint32_t off) {
    return off ^ (((off >> 7) & 3u) << 4);
}

// ---------------------------------------------------------------------------
// HMMA fp16 GEMM (unchanged from R12)
// ---------------------------------------------------------------------------
#define BK 32
#define NKI (DIM/BK)             // 16 k-iterations
#define GTILE_B 8192             // bytes per tile (128 rows x 64B)
#define GSTAGES 3

struct __align__(128) GemmSmem { char buf[GSTAGES][2][GTILE_B]; };  // 48 KB

__device__ __forceinline__ void gemm_load(uint32_t sbase, int stage, int c,
                                          const __half* A, const __half* B,
                                          int row0, int col0, int tid) {
    const int r = tid >> 1;
    const int h = tid & 1;
    const uint32_t so0 = swz((uint32_t)(r * 64 + h * 32));
    const uint32_t so1 = swz((uint32_t)(r * 64 + h * 32 + 16));
    const size_t ga = (size_t)(row0 + r) * DIM + c * BK + h * 16;
    const size_t gb = (size_t)(col0 + r) * DIM + c * BK + h * 16;
    const uint32_t base = sbase + (uint32_t)(stage * 2 * GTILE_B);
    cp16(base + 0 * GTILE_B + so0, A + ga);
    cp16(base + 0 * GTILE_B + so1, A + ga + 8);
    cp16(base + 1 * GTILE_B + so0, B + gb);
    cp16(base + 1 * GTILE_B + so1, B + gb + 8);
}

__device__ __forceinline__ void gemm_body(const __half* __restrict__ A,
                                          const __half* __restrict__ B,
                                          float* __restrict__ C) {
    __shared__ GemmSmem sm;
    const uint32_t sbase = smem_to_u32(&sm);
    const int tid = threadIdx.x;
    const int lane = tid & 31;
    const int wid = tid >> 5;
    const int warp_m = wid >> 1;
    const int warp_n = wid & 1;
    const int row0 = blockIdx.y * 128;
    const int col0 = blockIdx.x * 128;

    const int lr = lane & 15;
    const int lc = (lane >> 4) & 1;

    float acc[2][8][4];
    #pragma unroll
    for (int m = 0; m < 2; m++)
        #pragma unroll
        for (int n = 0; n < 8; n++)
            #pragma unroll
            for (int q = 0; q < 4; q++) acc[m][n][q] = 0.0f;

    #pragma unroll
    for (int s = 0; s < GSTAGES - 1; ++s) {
        gemm_load(sbase, s, s, A, B, row0, col0, tid);
        cp_commit();
    }

    uint32_t aAddr[2][2], bAddr[4][2];
    #pragma unroll
    for (int m = 0; m < 2; m++)
        #pragma unroll
        for (int kk = 0; kk < 2; kk++)
            aAddr[m][kk] = swz((uint32_t)((warp_m * 32 + m * 16 + lr) * 64
                                          + lc * 16 + kk * 32));
    #pragma unroll
    for (int q = 0; q < 4; q++)
        #pragma unroll
        for (int kk = 0; kk < 2; kk++)
            bAddr[q][kk] = swz((uint32_t)((warp_n * 64 + q * 16 + lr) * 64
                                          + lc * 16 + kk * 32));

    for (int c = 0; c < NKI; ++c) {
        cp_wait<GSTAGES - 2>();
        __syncthreads();

        if (c + GSTAGES - 1 < NKI)
            gemm_load(sbase, (c + GSTAGES - 1) % GSTAGES, c + GSTAGES - 1,
                      A, B, row0, col0, tid);
        cp_commit();

        const uint32_t bb = sbase + (uint32_t)((c % GSTAGES) * 2 * GTILE_B);

        #pragma unroll
        for (int kk = 0; kk < 2; ++kk) {
            uint32_t a[2][4], b[8][2];
            #pragma unroll
            for (int q = 0; q < 4; q++) {
                uint32_t t4[4];
                ldsm4(t4, bb + 1 * GTILE_B + bAddr[q][kk]);
                b[2*q][0] = t4[0]; b[2*q+1][0] = t4[1];
                b[2*q][1] = t4[2]; b[2*q+1][1] = t4[3];
            }
            ldsm4(a[0], bb + aAddr[0][kk]);
            ldsm4(a[1], bb + aAddr[1][kk]);
            #pragma unroll
            for (int m = 0; m < 2; m++)
                #pragma unroll
                for (int n = 0; n < 8; n++) mma16816(acc[m][n], a[m], b[n]);
        }
    }

    const int tr = lane >> 2;
    const int tc = (lane & 3) * 2;
    #pragma unroll
    for (int m = 0; m < 2; m++) {
        const int rbase = row0 + warp_m * 32 + m * 16 + tr;
        #pragma unroll
        for (int n = 0; n < 8; n++) {
            const int col = col0 + warp_n * 64 + n * 8 + tc;
            float* p0 = C + (size_t)rbase * DIM + col;
            float* p1 = C + (size_t)(rbase + 8) * DIM + col;
            *(float2*)p0 = make_float2(acc[m][n][0], acc[m][n][1]);
            *(float2*)p1 = make_float2(acc[m][n][2], acc[m][n][3]);
        }
    }
}

__global__ __launch_bounds__(256, 2) void gemm1_kernel() {
    gemm_body(g_xh, g_wi, g_i);
}
__global__ __launch_bounds__(256, 2) void gemm2_kernel(float* __restrict__ out) {
    gemm_body(g_yh, g_wo, out);
}

// ---------------------------------------------------------------------------
// es via HMMA (unchanged)
// ---------------------------------------------------------------------------
#define ETILE_B 4096
#define ES_PITCH 520
#define ESTAGES 3
#define ENKI 32

struct __align__(128) EsSmem {
    char abuf[ESTAGES][ETILE_B];
    __half w[16 * ES_PITCH];
};

__device__ __forceinline__ void es_load(uint32_t sbase, int stage, int c,
                                        int row0, int r) {
    #pragma unroll
    for (int h = 0; h < 2; ++h) {
        cp16(sbase + (uint32_t)(stage * ETILE_B)
                   + swz((uint32_t)(r * 32 + h * 16)),
             g_xh + (size_t)(row0 + r) * DIM + c * 16 + h * 8);
    }
}

__global__ __launch_bounds__(128, 4) void es_mma_kernel() {
    __shared__ EsSmem sm;
    const uint32_t sbase = smem_to_u32(&sm);
    const uint32_t wbase = smem_to_u32(sm.w);
    const int tid = threadIdx.x;
    const int lane = tid & 31;
    const int wid = tid >> 5;
    const int row0 = blockIdx.x * 128;
    const int r = tid;

    {
        const int row = tid >> 3;
        const int colb = (tid & 7) * 64;
        #pragma unroll
        for (int q = 0; q < 8; ++q) {
            uint4 v = *(const uint4*)(g_wes + row * DIM + colb + q * 8);
            *(uint4*)(sm.w + row * ES_PITCH + colb + q * 8) = v;
        }
    }

    #pragma unroll
    for (int s = 0; s < ESTAGES - 1; ++s) {
        es_load(sbase, s, s, row0, r);
        cp_commit();
    }

    const int lr = lane & 15;
    const int lc = (lane >> 4) & 1;
    uint32_t aAddr[2];
    #pragma unroll
    for (int m = 0; m < 2; m++)
        aAddr[m] = swz((uint32_t)((wid * 32 + m * 16 + lr) * 32 + lc * 16));

    float acc[2][2][4];
    #pragma unroll
    for (int m = 0; m < 2; m++)
        #pragma unroll
        for (int n = 0; n < 2; n++)
            #pragma unroll
            for (int q = 0; q < 4; q++) acc[m][n][q] = 0.0f;

    for (int c = 0; c < ENKI; ++c) {
        cp_wait<ESTAGES - 2>();
        __syncthreads();

        if (c + ESTAGES - 1 < ENKI) {
            int st = (c + ESTAGES - 1) % ESTAGES;
            es_load(sbase, st, c + ESTAGES - 1, row0, r);
        }
        cp_commit();

        uint32_t b[2][2];
        #pragma unroll
        for (int nt = 0; nt < 2; ++nt) {
            const uint32_t base = wbase
                + (uint32_t)(((nt * 8 + (lane >> 2)) * ES_PITCH + c * 16 + (lane & 3) * 2) * 2);
            asm volatile("ld.shared.b32 %0, [%1];" : "=r"(b[nt][0]) : "r"(base));
            asm volatile("ld.shared.b32 %0, [%1];" : "=r"(b[nt][1]) : "r"(base + 16));
        }

        const uint32_t ab = sbase + (uint32_t)((c % ESTAGES) * ETILE_B);
        uint32_t a[4];
        #pragma unroll
        for (int m = 0; m < 2; m++) {
            ldsm4(a, ab + aAddr[m]);
            mma16816(acc[m][0], a, b[0]);
            mma16816(acc[m][1], a, b[1]);
        }
    }

    const int tr = lane >> 2;
    const int tc = (lane & 3) * 2;
    #pragma unroll
    for (int m = 0; m < 2; m++) {
        const int rbase = row0 + wid * 32 + m * 16 + tr;
        #pragma unroll
        for (int nt = 0; nt < 2; nt++) {
            float* dst = nt ? g_s : g_e;
            *(float2*)(dst + (size_t)rbase * KEXP + tc) =
                make_float2(acc[m][nt][0], acc[m][nt][1]);
            *(float2*)(dst + (size_t)(rbase + 8) * KEXP + tc) =
                make_float2(acc[m][nt][2], acc[m][nt][3]);
        }
    }
}

// ---------------------------------------------------------------------------
// Fused conversions (unchanged)
// ---------------------------------------------------------------------------
#define CVT_XBLOCKS (ROWS * DIM / 4 / 256)   // 8192

__global__ __launch_bounds__(256) void convert_all_kernel(
        const float* __restrict__ x,
        const float* __restrict__ W_i, const float* __restrict__ W_out,
        const float* __restrict__ W_e, const float* __restrict__ W_s) {
    __shared__ float t[32][33];
    const int bid = blockIdx.x;
    const int tid = threadIdx.x;

    if (bid < CVT_XBLOCKS) {
        const size_t i = (size_t)bid * 256 + tid;
        float4 v = ((const float4*)x)[i];
        __half h[4];
        h[0] = __float2half(v.x);
        h[1] = __float2half(v.y);
        h[2] = __float2half(v.z);
        h[3] = __float2half(v.w);
        ((uint2*)g_xh)[i] = *(uint2*)h;
    } else if (bid < CVT_XBLOCKS + 512) {
        const int idx = bid - CVT_XBLOCKS;
        const int z = idx >> 8;
        const float* W = z ? W_out : W_i;
        __half* D = z ? g_wo : g_wi;
        const int n0 = (idx & 15) * 32;
        const int k0 = ((idx >> 4) & 15) * 32;
        const int tx = tid & 31, ty = tid >> 5;
        #pragma unroll
        for (int j = 0; j < 4; ++j)
            t[ty + j * 8][tx] = W[(size_t)(k0 + ty + j * 8) * DIM + n0 + tx];
        __syncthreads();
        #pragma unroll
        for (int j = 0; j < 4; ++j) {
            const int nn = ty + j * 8;
            D[(size_t)(n0 + nn) * DIM + k0 + tx] = __float2half(t[tx][nn]);
        }
    } else {
        for (int e = tid; e < 16 * DIM; e += 256) {
            const int j = e >> 9, d = e & 511;
            const float v = (j < 8) ? W_e[d * KEXP + j] : W_s[d * KEXP + j - 8];
            g_wes[e] = __float2half(v);
        }
    }
}

// ---------------------------------------------------------------------------
// Decay helper (2 adjacent d-columns)
// ---------------------------------------------------------------------------
__device__ __forceinline__ void load_decay2(const float* __restrict__ o_param,
                                            int d0, float scale, float o[KEXP][2]) {
    #pragma unroll
    for (int k = 0; k < KEXP; k++) {
        float2 op = *(const float2*)(o_param + k * DIM + d0);
        float ls0 = fminf(op.x, 0.0f) - log1pf(expf(-fabsf(op.x)));
        float ls1 = fminf(op.y, 0.0f) - log1pf(expf(-fabsf(op.y)));
        o[k][0] = expf(ls0 * scale);
        o[k][1] = expf(ls1 * scale);
    }
}

// ---------------------------------------------------------------------------
// Scan phase 1: per-chunk local end state.
// 128 threads x 2 d-columns; CTA covers 256 d (grid z splits d).
// e chunk (4KB) staged in SMEM once; iv via 3-stage cp.async ring (8KB/stage).
// FMA order per (k,d) chain unchanged -> bit-identical numerics.
// ---------------------------------------------------------------------------
#define SL_TG 8
#define SL_STAGES 3
#define SL_NS (CHUNK/SL_TG)     // 16
#define SL_D 256                // d-columns per CTA

__global__ __launch_bounds__(128) void scan_local_kernel(const float* __restrict__ o_param) {
    __shared__ float es[CHUNK * KEXP];                 // 4 KB
    __shared__ float ivb[SL_STAGES][SL_TG][SL_D];      // 24 KB
    const uint32_t es_u = smem_to_u32(es);
    const uint32_t ivb_u = smem_to_u32(ivb);
    const int c = blockIdx.x, b = blockIdx.y, dz = blockIdx.z;
    const int tid = threadIdx.x;
    const int d0 = dz * SL_D + 2 * tid;

    float o[KEXP][2], m[KEXP][2];
    load_decay2(o_param, d0, INV_TAU, o);
    #pragma unroll
    for (int k = 0; k < KEXP; k++) { m[k][0] = 0.0f; m[k][1] = 0.0f; }

    const size_t rowbase = (size_t)b * SEQ + c * CHUNK;
    const float* ibase = g_i + rowbase * DIM + dz * SL_D;
    const float* ep = g_e + rowbase * KEXP;

    // Prologue group 0: e chunk + iv stage 0
    #pragma unroll
    for (int i = 0; i < 2; ++i)
        cp16(es_u + (uint32_t)((tid + i * 128) * 16), ep + (tid + i * 128) * 4);
    #pragma unroll
    for (int i = 0; i < 4; ++i) {
        const int q = tid + i * 128;            // 0..511
        const int tl = q >> 6, col = (q & 63) * 4;
        cp16(ivb_u + (uint32_t)((tl * SL_D + col) * 4),
             ibase + (size_t)tl * DIM + col);
    }
    cp_commit();
    // Prologue group 1: iv stage 1
    #pragma unroll
    for (int i = 0; i < 4; ++i) {
        const int q = tid + i * 128;
        const int tl = q >> 6, col = (q & 63) * 4;
        cp16(ivb_u + (uint32_t)(((SL_TG + tl) * SL_D + col) * 4),
             ibase + (size_t)(SL_TG + tl) * DIM + col);
    }
    cp_commit();

    for (int s = 0; s < SL_NS; ++s) {
        cp_wait<SL_STAGES - 2>();
        __syncthreads();

        if (s + SL_STAGES - 1 < SL_NS) {
            const int ns = s + SL_STAGES - 1;
            const int st = ns % SL_STAGES;
            #pragma unroll
            for (int i = 0; i < 4; ++i) {
                const int q = tid + i * 128;
                const int tl = q >> 6, col = (q & 63) * 4;
                cp16(ivb_u + (uint32_t)(((st * SL_TG + tl) * SL_D + col) * 4),
                     ibase + (size_t)(ns * SL_TG + tl) * DIM + col);
            }
        }
        cp_commit();

        const int st = s % SL_STAGES;
        #pragma unroll
        for (int j = 0; j < SL_TG; ++j) {
            const int t = s * SL_TG + j;
            const float2 iv = *(const float2*)(&ivb[st][j][2 * tid]);
            const float4 e0 = *(const float4*)(es + t * KEXP);
            const float4 e1 = *(const float4*)(es + t * KEXP + 4);
            const float ev[KEXP] = {e0.x, e0.y, e0.z, e0.w, e1.x, e1.y, e1.z, e1.w};
            #pragma unroll
            for (int k = 0; k < KEXP; k++) {
                m[k][0] = fmaf(o[k][0], m[k][0], ev[k] * iv.x);
                m[k][1] = fmaf(o[k][1], m[k][1], ev[k] * iv.y);
            }
        }
    }
    #pragma unroll
    for (int k = 0; k < KEXP; k++)
        *(float2*)(g_S + (((size_t)b * NCHUNK + c) * KEXP + k) * DIM + d0) =
            make_float2(m[k][0], m[k][1]);
}

// ---------------------------------------------------------------------------
// Scan phase 2: prefix over chunks (unchanged)
// ---------------------------------------------------------------------------
__global__ __launch_bounds__(DIM) void scan_prefix_kernel(const float* __restrict__ o_param) {
    const int b = blockIdx.x;
    const int kp = blockIdx.y * 2;
    const int d = threadIdx.x;

    float oL0, oL1;
    {
        float op0 = o_param[kp * DIM + d];
        float op1 = o_param[(kp + 1) * DIM + d];
        float ls0 = fminf(op0, 0.0f) - log1pf(expf(-fabsf(op0)));
        float ls1 = fminf(op1, 0.0f) - log1pf(expf(-fabsf(op1)));
        oL0 = expf(ls0 * (INV_TAU * (float)CHUNK));
        oL1 = expf(ls1 * (INV_TAU * (float)CHUNK));
    }

    float s0[NCHUNK], s1[NCHUNK];
    #pragma unroll
    for (int c = 0; c < NCHUNK; c++) {
        s0[c] = g_S[(((size_t)b * NCHUNK + c) * KEXP + kp) * DIM + d];
        s1[c] = g_S[(((size_t)b * NCHUNK + c) * KEXP + kp + 1) * DIM + d];
    }
    float p0 = 0.0f, p1 = 0.0f;
    #pragma unroll
    for (int c = 0; c < NCHUNK; c++) {
        g_P[(((size_t)b * NCHUNK + c) * KEXP + kp) * DIM + d] = p0;
        g_P[(((size_t)b * NCHUNK + c) * KEXP + kp + 1) * DIM + d] = p1;
        p0 = fmaf(oL0, p0, s0[c]);
        p1 = fmaf(oL1, p1, s1[c]);
    }
}

// ---------------------------------------------------------------------------
// Scan phase 3 + LayerNorm. 256 threads x 2 d-columns (full 512 d for LN).
// e+s chunks (8KB) staged once; iv via 2-stage ring (32KB/stage).
// Dynamic SMEM layout: ybuf[16][512] | es[1024] | ss[1024] | ivb[2][16][512]
// ---------------------------------------------------------------------------
#define TG 16
#define AP_GROUPS (CHUNK/TG)          // 8
#define AP_DYN ((TG*DIM + 2*CHUNK*KEXP + 2*TG*DIM) * 4)   // 106496 B

__global__ __launch_bounds__(256) void scan_apply_ln_kernel(const float* __restrict__ o_param,
                                                            const float* __restrict__ gamma,
                                                            const float* __restrict__ beta) {
    extern __shared__ float dyn[];
    float (*ybuf)[DIM] = (float(*)[DIM])dyn;
    float* es = dyn + TG * DIM;
    float* ss = es + CHUNK * KEXP;
    float* ivb = ss + CHUNK * KEXP;           // [2][TG][DIM]
    const uint32_t es_u = smem_to_u32(es);
    const uint32_t ss_u = smem_to_u32(ss);
    const uint32_t ivb_u = smem_to_u32(ivb);
    __shared__ float smu[TG], srstd[TG];

    const int c = blockIdx.x, b = blockIdx.y;
    const int tid = threadIdx.x;
    const int d0 = 2 * tid;
    const int lane = tid & 31, warp = tid >> 5;   // 8 warps

    float o[KEXP][2], m[KEXP][2];
    load_decay2(o_param, d0, INV_TAU, o);
    #pragma unroll
    for (int k = 0; k < KEXP; k++) {
        float2 p = *(const float2*)(g_P + (((size_t)b * NCHUNK + c) * KEXP + k) * DIM + d0);
        m[k][0] = p.x; m[k][1] = p.y;
    }

    const float2 gam = *(const float2*)(gamma + d0);
    const float2 bet = *(const float2*)(beta + d0);

    const size_t rowbase = (size_t)b * SEQ + c * CHUNK;
    const float* ibase = g_i + rowbase * DIM;
    const float* ep = g_e + rowbase * KEXP;
    const float* sp = g_s + rowbase * KEXP;

    // Prologue: e chunk + s chunk + iv stage 0 (one commit group)
    cp16(es_u + (uint32_t)(tid * 16), ep + tid * 4);
    cp16(ss_u + (uint32_t)(tid * 16), sp + tid * 4);
    #pragma unroll
    for (int i = 0; i < 8; ++i) {
        const int q = tid + i * 256;               // 0..2047
        const int tl = q >> 7, col = (q & 127) * 4;
        cp16(ivb_u + (uint32_t)((tl * DIM + col) * 4),
             ibase + (size_t)tl * DIM + col);
    }
    cp_commit();

    for (int g = 0; g < AP_GROUPS; ++g) {
        cp_wait<0>();
        __syncthreads();

        if (g + 1 < AP_GROUPS) {
            const int st = (g + 1) & 1;
            #pragma unroll
            for (int i = 0; i < 8; ++i) {
                const int q = tid + i * 256;
                const int tl = q >> 7, col = (q & 127) * 4;
                cp16(ivb_u + (uint32_t)(((st * TG + tl) * DIM + col) * 4),
                     ibase + (size_t)((g + 1) * TG + tl) * DIM + col);
            }
        }
        cp_commit();

        const float* ivst = ivb + (size_t)(g & 1) * TG * DIM;

        #pragma unroll 4
        for (int tt = 0; tt < TG; ++tt) {
            const int t = g * TG + tt;
            const float2 iv = *(const float2*)(ivst + tt * DIM + d0);
            const float4 e0 = *(const float4*)(es + t * KEXP);
            const float4 e1 = *(const float4*)(es + t * KEXP + 4);
            const float4 s0 = *(const float4*)(ss + t * KEXP);
            const float4 s1 = *(const float4*)(ss + t * KEXP + 4);
            const float ev[KEXP] = {e0.x, e0.y, e0.z, e0.w, e1.x, e1.y, e1.z, e1.w};
            const float sv[KEXP] = {s0.x, s0.y, s0.z, s0.w, s1.x, s1.y, s1.z, s1.w};
            float ya0 = 0.0f, ya1 = 0.0f;
            #pragma unroll
            for (int k = 0; k < KEXP; k++) {
                m[k][0] = fmaf(o[k][0], m[k][0], ev[k] * iv.x);
                m[k][1] = fmaf(o[k][1], m[k][1], ev[k] * iv.y);
                ya0 = fmaf(sv[k], m[k][0], ya0);
                ya1 = fmaf(sv[k], m[k][1], ya1);
            }
            ybuf[tt][d0] = ya0;
            ybuf[tt][d0 + 1] = ya1;
        }
        __syncthreads();

        // 8 warps: warp w reduces timesteps 2w and 2w+1
        #pragma unroll
        for (int h = 0; h < 2; ++h) {
            const int tt = warp * 2 + h;
            float s1r = 0.0f, s2r = 0.0f;
            #pragma unroll
            for (int j = 0; j < 16; ++j) {
                const float v = ybuf[tt][lane + j * 32];
                s1r += v;
                s2r = fmaf(v, v, s2r);
            }
            #pragma unroll
            for (int off = 16; off > 0; off >>= 1) {
                s1r += __shfl_xor_sync(0xFFFFFFFFu, s1r, off);
                s2r += __shfl_xor_sync(0xFFFFFFFFu, s2r, off);
            }
            if (lane == 0) {
                const float mu = s1r * (1.0f / DIM);
                const float var = s2r * (1.0f / DIM) - mu * mu;
                smu[tt] = mu;
                srstd[tt] = rsqrtf(var + LN_EPS);
            }
        }
        __syncthreads();

        #pragma unroll 4
        for (int tt = 0; tt < TG; ++tt) {
            const size_t row = rowbase + g * TG + tt;
            const float rv0 = fmaf((ybuf[tt][d0] - smu[tt]) * srstd[tt], gam.x, bet.x);
            const float rv1 = fmaf((ybuf[tt][d0 + 1] - smu[tt]) * srstd[tt], gam.y, bet.y);
            *(__half2*)(g_yh + row * DIM + d0) = __floats2half2_rn(rv0, rv1);
        }
    }
}

// ---------------------------------------------------------------------------
// Launch
// ---------------------------------------------------------------------------
extern "C" void kernel_launch(void* const* d_in, const int* in_sizes, int n_in,
                              void* d_out, int out_size) {
    const float* x       = (const float*)d_in[0];
    const float* W_i     = (const float*)d_in[1];
    const float* W_e     = (const float*)d_in[2];
    const float* W_s     = (const float*)d_in[3];
    const float* o_param = (const float*)d_in[4];
    const float* gamma   = (const float*)d_in[5];
    const float* beta    = (const float*)d_in[6];
    const float* W_out   = (const float*)d_in[7];
    float* out = (float*)d_out;

    cudaFuncSetAttribute(scan_apply_ln_kernel,
                         cudaFuncAttributeMaxDynamicSharedMemorySize, AP_DYN);

    convert_all_kernel<<<CVT_XBLOCKS + 512 + 1, 256>>>(x, W_i, W_out, W_e, W_s);
    gemm1_kernel<<<dim3(4, 128), 256>>>();
    es_mma_kernel<<<128, 128>>>();
    scan_local_kernel<<<dim3(NCHUNK, BATCH, 2), 128>>>(o_param);
    scan_prefix_kernel<<<dim3(BATCH, KEXP / 2), DIM>>>(o_param);
    scan_apply_ln_kernel<<<dim3(NCHUNK, BATCH), 256, AP_DYN>>>(o_param, gamma, beta);
    gemm2_kernel<<<dim3(4, 128), 256>>>(out);
}